// round 1
// baseline (speedup 1.0000x reference)
#include <cuda_runtime.h>

#define NA 10000
#define NE 320000
#define HD 128
#define NR 50
#define NL 6
#define CUTR 5.0f

#define NWARPS 16     // warps per block in edge kernels (512 threads)
#define EPW 8         // edges per warp pass

// ---------------- scratch (device globals; no allocation APIs) ----------------
__device__ float g_C[NE];
__device__ float g_expd[NE];
__device__ int   g_act[NE];
__device__ int   g_nact;
__device__ float g_ea[(size_t)NE * NR];   // compacted edge_attr [k][r]
__device__ float g_x[NA * HD];
__device__ float g_msg[NA * HD];
__device__ float g_y[NA * HD];
__device__ float g_m[NA * HD];

__device__ __forceinline__ float silu_f(float x) {
    // x * sigmoid(x); for x << 0, expf(-x)=inf -> x/inf = 0 (correct limit)
    return x / (1.0f + __expf(-x));
}

// ---------------- edge geometry ----------------
__global__ void geom_kernel(const int* __restrict__ ei, const float* __restrict__ pos) {
    int e = blockIdx.x * blockDim.x + threadIdx.x;
    if (e >= NE) return;
    int s = ei[e], d = ei[NE + e];
    float dx = pos[3 * s + 0] - pos[3 * d + 0];
    float dy = pos[3 * s + 1] - pos[3 * d + 1];
    float dz = pos[3 * s + 2] - pos[3 * d + 2];
    float dist = sqrtf(dx * dx + dy * dy + dz * dz + 1e-12f);
    float C = 0.f;
    if (dist < CUTR) C = 0.5f * (cosf(3.14159265358979323846f * dist / CUTR) + 1.f);
    g_C[e] = C;
    g_expd[e] = expf(-dist);
}

__global__ void compact_kernel() {
    int e = blockIdx.x * blockDim.x + threadIdx.x;
    if (e >= NE) return;
    if (g_C[e] > 0.f) {
        int k = atomicAdd(&g_nact, 1);
        g_act[k] = e;
    }
}

__global__ void attr_kernel(const float* __restrict__ means, const float* __restrict__ betas) {
    long idx = (long)blockIdx.x * blockDim.x + threadIdx.x;
    if (idx >= (long)NE * NR) return;
    int k = (int)(idx / NR);
    if (k >= g_nact) return;
    int r = (int)(idx - (long)k * NR);
    int e = g_act[k];
    float t = g_expd[e] - __ldg(&means[r]);
    g_ea[idx] = g_C[e] * expf(-__ldg(&betas[r]) * t * t);
}

// ---------------- atom embedding + zero msg ----------------
__global__ void embed_kernel(const int* __restrict__ z, const float* __restrict__ emb) {
    int idx = blockIdx.x * blockDim.x + threadIdx.x;
    if (idx >= NA * HD) return;
    int i = idx >> 7;
    g_x[idx] = emb[(long)z[i] * HD + (idx & 127)];
    g_msg[idx] = 0.f;
}

// ---------------- NeighborEmbedding edge kernel ----------------
__global__ __launch_bounds__(NWARPS * 32, 1)
void nbr_kernel(const int* __restrict__ ei, const int* __restrict__ z,
                const float* __restrict__ emb,
                const float* __restrict__ Wg, const float* __restrict__ bg) {
    extern __shared__ float sh[];
    float* sW = sh;                 // NR*HD
    float* sB = sW + NR * HD;       // HD
    float* sBuf = sB + HD;          // per-warp EPW*NR
    int tid = threadIdx.x;
    for (int i = tid; i < NR * HD; i += NWARPS * 32) sW[i] = Wg[i];
    if (tid < HD) sB[tid] = bg[tid];
    __syncthreads();
    int warp = tid >> 5, lane = tid & 31;
    float* sEA = sBuf + warp * (EPW * NR);
    const int nact = g_nact;
    int gw = blockIdx.x * NWARPS + warp;
    int stride = gridDim.x * NWARPS;
    float4 b4 = *(float4*)&sB[4 * lane];
    for (int base = gw * EPW; base < nact; base += stride * EPW) {
        __syncwarp();
        int src = 0, dst = 0; float Ce = 0.f;
        if (lane < EPW && base + lane < nact) {
            int e = g_act[base + lane];
            src = ei[e]; dst = ei[NE + e]; Ce = g_C[e];
        }
        for (int i = lane; i < EPW * NR; i += 32) {
            long gi = (long)base * NR + i;
            sEA[i] = (gi < (long)nact * NR) ? g_ea[gi] : 0.f;
        }
        __syncwarp();
        float4 acc[EPW];
        #pragma unroll
        for (int e = 0; e < EPW; e++) acc[e] = make_float4(0.f, 0.f, 0.f, 0.f);
        #pragma unroll 2
        for (int r = 0; r < NR; r++) {
            float4 w = *(float4*)&sW[r * HD + 4 * lane];
            #pragma unroll
            for (int e = 0; e < EPW; e++) {
                float a = sEA[e * NR + r];
                acc[e].x = fmaf(a, w.x, acc[e].x);
                acc[e].y = fmaf(a, w.y, acc[e].y);
                acc[e].z = fmaf(a, w.z, acc[e].z);
                acc[e].w = fmaf(a, w.w, acc[e].w);
            }
        }
        int valid = min(EPW, nact - base);
        for (int e = 0; e < valid; e++) {
            int s = __shfl_sync(0xffffffffu, src, e);
            int d = __shfl_sync(0xffffffffu, dst, e);
            float c = __shfl_sync(0xffffffffu, Ce, e);
            if (s == d) continue;   // self-loops removed in NeighborEmbedding
            int zs = __ldg(&z[s]);
            float4 em = *(const float4*)&emb[(long)zs * HD + 4 * lane];
            float4 wn;
            wn.x = (acc[e].x + b4.x) * c;
            wn.y = (acc[e].y + b4.y) * c;
            wn.z = (acc[e].z + b4.z) * c;
            wn.w = (acc[e].w + b4.w) * c;
            float* p = &g_msg[(long)d * HD + 4 * lane];
            atomicAdd(p + 0, em.x * wn.x);
            atomicAdd(p + 1, em.y * wn.y);
            atomicAdd(p + 2, em.z * wn.z);
            atomicAdd(p + 3, em.w * wn.w);
        }
    }
}

// ---------------- combine: x = [x, msg] @ W(256x128) + b ----------------
__global__ __launch_bounds__(256, 1)
void comb_kernel(const float* __restrict__ W, const float* __restrict__ bg) {
    extern __shared__ float sh[];
    float* sW = sh;                 // 256*HD
    float* sB = sW + 256 * HD;      // HD
    float* sXb = sB + HD;           // 8 warps * 1024
    int tid = threadIdx.x;
    for (int i = tid; i < 256 * HD; i += 256) sW[i] = W[i];
    if (tid < HD) sB[tid] = bg[tid];
    __syncthreads();
    int warp = tid >> 5, lane = tid & 31;
    float* sX = sXb + warp * 1024;
    int gw = blockIdx.x * 8 + warp, nw = gridDim.x * 8;
    for (int n0 = gw * 4; n0 < NA; n0 += nw * 4) {
        __syncwarp();
        for (int i = lane; i < 1024; i += 32) {
            int n = i >> 8, h = i & 255; int node = n0 + n;
            float v = 0.f;
            if (node < NA) v = (h < HD) ? g_x[node * HD + h] : g_msg[node * HD + h - HD];
            sX[i] = v;
        }
        __syncwarp();
        float4 b4 = *(float4*)&sB[4 * lane];
        float4 acc[4];
        #pragma unroll
        for (int n = 0; n < 4; n++) acc[n] = b4;
        #pragma unroll 2
        for (int r = 0; r < 256; r++) {
            float4 w = *(float4*)&sW[r * HD + 4 * lane];
            #pragma unroll
            for (int n = 0; n < 4; n++) {
                float a = sX[n * 256 + r];
                acc[n].x = fmaf(a, w.x, acc[n].x);
                acc[n].y = fmaf(a, w.y, acc[n].y);
                acc[n].z = fmaf(a, w.z, acc[n].z);
                acc[n].w = fmaf(a, w.w, acc[n].w);
            }
        }
        #pragma unroll
        for (int n = 0; n < 4; n++) {
            int node = n0 + n;
            if (node >= NA) break;
            *(float4*)&g_x[node * HD + 4 * lane] = acc[n];
        }
    }
}

// ---------------- CFConv fused edge kernel ----------------
__global__ __launch_bounds__(NWARPS * 32, 1)
void cfconv_kernel(const int* __restrict__ ei,
                   const float* __restrict__ W1g, const float* __restrict__ b1g,
                   const float* __restrict__ W2g, const float* __restrict__ b2g) {
    extern __shared__ float sh[];
    float* sW1 = sh;                // 6400
    float* sB1 = sW1 + NR * HD;     // 128
    float* sW2 = sB1 + HD;          // 16384
    float* sB2 = sW2 + HD * HD;     // 128
    float* sBuf = sB2 + HD;         // per-warp EPW*NR + EPW*132
    int tid = threadIdx.x;
    for (int i = tid; i < NR * HD; i += NWARPS * 32) sW1[i] = W1g[i];
    for (int i = tid; i < HD * HD; i += NWARPS * 32) sW2[i] = W2g[i];
    if (tid < HD) { sB1[tid] = b1g[tid]; sB2[tid] = b2g[tid]; }
    __syncthreads();
    int warp = tid >> 5, lane = tid & 31;
    float* sEA = sBuf + warp * (EPW * NR + EPW * 132);
    float* sH1 = sEA + EPW * NR;    // [e*132 + r], padded stride
    const int nact = g_nact;
    int gw = blockIdx.x * NWARPS + warp;
    int stride = gridDim.x * NWARPS;
    float4 b1v = *(float4*)&sB1[4 * lane];
    float4 b2v = *(float4*)&sB2[4 * lane];
    for (int base = gw * EPW; base < nact; base += stride * EPW) {
        __syncwarp();
        int src = 0, dst = 0; float Ce = 0.f;
        if (lane < EPW && base + lane < nact) {
            int e = g_act[base + lane];
            src = ei[e]; dst = ei[NE + e]; Ce = g_C[e];
        }
        for (int i = lane; i < EPW * NR; i += 32) {
            long gi = (long)base * NR + i;
            sEA[i] = (gi < (long)nact * NR) ? g_ea[gi] : 0.f;
        }
        __syncwarp();
        float4 acc[EPW];
        #pragma unroll
        for (int e = 0; e < EPW; e++) acc[e] = make_float4(0.f, 0.f, 0.f, 0.f);
        // phase B: h1 = silu(EA @ W1 + b1)
        #pragma unroll 2
        for (int r = 0; r < NR; r++) {
            float4 w = *(float4*)&sW1[r * HD + 4 * lane];
            #pragma unroll
            for (int e = 0; e < EPW; e++) {
                float a = sEA[e * NR + r];
                acc[e].x = fmaf(a, w.x, acc[e].x);
                acc[e].y = fmaf(a, w.y, acc[e].y);
                acc[e].z = fmaf(a, w.z, acc[e].z);
                acc[e].w = fmaf(a, w.w, acc[e].w);
            }
        }
        #pragma unroll
        for (int e = 0; e < EPW; e++) {
            int c0 = e * 132 + 4 * lane;
            sH1[c0 + 0] = silu_f(acc[e].x + b1v.x);
            sH1[c0 + 1] = silu_f(acc[e].y + b1v.y);
            sH1[c0 + 2] = silu_f(acc[e].z + b1v.z);
            sH1[c0 + 3] = silu_f(acc[e].w + b1v.w);
            acc[e] = make_float4(0.f, 0.f, 0.f, 0.f);
        }
        __syncwarp();
        // phase C: wf = (h1 @ W2 + b2) * C
        #pragma unroll 2
        for (int r = 0; r < HD; r++) {
            float4 w = *(float4*)&sW2[r * HD + 4 * lane];
            #pragma unroll
            for (int e = 0; e < EPW; e++) {
                float a = sH1[e * 132 + r];
                acc[e].x = fmaf(a, w.x, acc[e].x);
                acc[e].y = fmaf(a, w.y, acc[e].y);
                acc[e].z = fmaf(a, w.z, acc[e].z);
                acc[e].w = fmaf(a, w.w, acc[e].w);
            }
        }
        int valid = min(EPW, nact - base);
        for (int e = 0; e < valid; e++) {
            int s = __shfl_sync(0xffffffffu, src, e);
            int d = __shfl_sync(0xffffffffu, dst, e);
            float c = __shfl_sync(0xffffffffu, Ce, e);
            float4 yv = *(const float4*)&g_y[(long)s * HD + 4 * lane];
            float4 wf;
            wf.x = (acc[e].x + b2v.x) * c;
            wf.y = (acc[e].y + b2v.y) * c;
            wf.z = (acc[e].z + b2v.z) * c;
            wf.w = (acc[e].w + b2v.w) * c;
            float* p = &g_m[(long)d * HD + 4 * lane];
            atomicAdd(p + 0, yv.x * wf.x);
            atomicAdd(p + 1, yv.y * wf.y);
            atomicAdd(p + 2, yv.z * wf.z);
            atomicAdd(p + 3, yv.w * wf.w);
        }
    }
}

// ---------------- generic node GEMM: out = act(X @ W + b) [+ addsrc] ----------------
__global__ __launch_bounds__(256, 2)
void node_mm128(const float* __restrict__ X, const float* __restrict__ W,
                const float* __restrict__ bg, const float* __restrict__ addsrc,
                float* __restrict__ out, int act) {
    extern __shared__ float sh[];
    float* sW = sh;                 // HD*HD
    float* sB = sW + HD * HD;       // HD
    float* sXb = sB + HD;           // 8 warps * 512
    int tid = threadIdx.x;
    for (int i = tid; i < HD * HD; i += 256) sW[i] = W[i];
    if (tid < HD) sB[tid] = bg ? bg[tid] : 0.f;
    __syncthreads();
    int warp = tid >> 5, lane = tid & 31;
    float* sX = sXb + warp * 512;
    int gw = blockIdx.x * 8 + warp, nw = gridDim.x * 8;
    for (int n0 = gw * 4; n0 < NA; n0 += nw * 4) {
        __syncwarp();
        for (int i = lane; i < 512; i += 32) {
            int n = i >> 7, h = i & 127; int node = n0 + n;
            sX[i] = (node < NA) ? X[node * HD + h] : 0.f;
        }
        __syncwarp();
        float4 b4 = *(float4*)&sB[4 * lane];
        float4 acc[4];
        #pragma unroll
        for (int n = 0; n < 4; n++) acc[n] = b4;
        #pragma unroll 2
        for (int r = 0; r < HD; r++) {
            float4 w = *(float4*)&sW[r * HD + 4 * lane];
            #pragma unroll
            for (int n = 0; n < 4; n++) {
                float a = sX[n * HD + r];
                acc[n].x = fmaf(a, w.x, acc[n].x);
                acc[n].y = fmaf(a, w.y, acc[n].y);
                acc[n].z = fmaf(a, w.z, acc[n].z);
                acc[n].w = fmaf(a, w.w, acc[n].w);
            }
        }
        #pragma unroll
        for (int n = 0; n < 4; n++) {
            int node = n0 + n;
            if (node >= NA) break;
            float4 v = acc[n];
            if (act) {
                v.x = silu_f(v.x); v.y = silu_f(v.y);
                v.z = silu_f(v.z); v.w = silu_f(v.w);
            }
            if (addsrc) {
                float4 o = *(const float4*)&addsrc[node * HD + 4 * lane];
                v.x += o.x; v.y += o.y; v.z += o.z; v.w += o.w;
            }
            *(float4*)&out[node * HD + 4 * lane] = v;
        }
    }
}

// ---------------- launcher ----------------
extern "C" void kernel_launch(void* const* d_in, const int* in_sizes, int n_in,
                              void* d_out, int out_size) {
    const int*   z      = (const int*)d_in[0];
    const float* pos    = (const float*)d_in[1];
    // d_in[2] = batch (unused)
    const int*   ei     = (const int*)d_in[3];
    const float* emb    = (const float*)d_in[4];
    const float* nemb   = (const float*)d_in[5];
    const float* nprojW = (const float*)d_in[6];
    const float* nprojB = (const float*)d_in[7];
    const float* ncombW = (const float*)d_in[8];
    const float* ncombB = (const float*)d_in[9];
    const float* means  = (const float*)d_in[10];
    const float* betas  = (const float*)d_in[11];
    const float* mlpW1  = (const float*)d_in[12];
    const float* mlpb1  = (const float*)d_in[13];
    const float* mlpW2  = (const float*)d_in[14];
    const float* mlpb2  = (const float*)d_in[15];
    const float* convW1 = (const float*)d_in[16];
    const float* convW2 = (const float*)d_in[17];
    const float* convb2 = (const float*)d_in[18];
    const float* linW   = (const float*)d_in[19];
    const float* linb   = (const float*)d_in[20];
    float* out = (float*)d_out;

    void *p_nact, *p_m, *p_x, *p_y, *p_msg;
    cudaGetSymbolAddress(&p_nact, g_nact);
    cudaGetSymbolAddress(&p_m, g_m);
    cudaGetSymbolAddress(&p_x, g_x);
    cudaGetSymbolAddress(&p_y, g_y);
    cudaGetSymbolAddress(&p_msg, g_msg);
    float* px = (float*)p_x;
    float* py = (float*)p_y;
    float* pm = (float*)p_m;

    size_t sh_nbr  = (size_t)(NR * HD + HD + NWARPS * EPW * NR) * sizeof(float);
    size_t sh_comb = (size_t)(256 * HD + HD + 8 * 1024) * sizeof(float);
    size_t sh_cf   = (size_t)(NR * HD + HD + HD * HD + HD + NWARPS * (EPW * NR + EPW * 132)) * sizeof(float);
    size_t sh_mm   = (size_t)(HD * HD + HD + 8 * 512) * sizeof(float);
    cudaFuncSetAttribute(nbr_kernel,    cudaFuncAttributeMaxDynamicSharedMemorySize, (int)sh_nbr);
    cudaFuncSetAttribute(comb_kernel,   cudaFuncAttributeMaxDynamicSharedMemorySize, (int)sh_comb);
    cudaFuncSetAttribute(cfconv_kernel, cudaFuncAttributeMaxDynamicSharedMemorySize, (int)sh_cf);
    cudaFuncSetAttribute(node_mm128,    cudaFuncAttributeMaxDynamicSharedMemorySize, (int)sh_mm);

    cudaMemsetAsync(p_nact, 0, sizeof(int));
    geom_kernel<<<(NE + 255) / 256, 256>>>(ei, pos);
    compact_kernel<<<(NE + 255) / 256, 256>>>();
    attr_kernel<<<(int)(((long)NE * NR + 255) / 256), 256>>>(means, betas);
    embed_kernel<<<(NA * HD + 255) / 256, 256>>>(z, emb);
    nbr_kernel<<<148, NWARPS * 32, sh_nbr>>>(ei, z, nemb, nprojW, nprojB);
    comb_kernel<<<148, 256, sh_comb>>>(ncombW, ncombB);

    for (int l = 0; l < NL; l++) {
        node_mm128<<<296, 256, sh_mm>>>(px, convW1 + (size_t)l * HD * HD, nullptr, nullptr, py, 0);
        cudaMemsetAsync(p_m, 0, (size_t)NA * HD * sizeof(float));
        cfconv_kernel<<<148, NWARPS * 32, sh_cf>>>(ei,
            mlpW1 + (size_t)l * NR * HD, mlpb1 + (size_t)l * HD,
            mlpW2 + (size_t)l * HD * HD, mlpb2 + (size_t)l * HD);
        node_mm128<<<296, 256, sh_mm>>>(pm, convW2 + (size_t)l * HD * HD,
                                        convb2 + (size_t)l * HD, nullptr, py, 1);
        float* dest = (l == NL - 1) ? out : px;
        node_mm128<<<296, 256, sh_mm>>>(py, linW + (size_t)l * HD * HD,
                                        linb + (size_t)l * HD, px, dest, 0);
    }
}

// round 2
// speedup vs baseline: 2.1958x; 2.1958x over previous
#include <cuda_runtime.h>

#define NA 10000
#define NE 320000
#define HD 128
#define NR 50
#define NL 6
#define NT 4096
#define CUTR 5.0f
#define PI_F 3.14159265358979f

// u = exp(-d) mapping constants (must match between build and lookup)
#define UMINF 0.0067379469990854670966f
#define INVTF ((1.0f - UMINF) / (float)(NT - 1))
#define SCALEF ((float)(NT - 1) / (1.0f - UMINF))

// ---------------- scratch (device globals; no allocation APIs) ----------------
__device__ int   g_cnt[NA];
__device__ int   g_off[NA + 1];
__device__ int   g_cur[NA];
__device__ int   g_csrc[NE];
__device__ float g_cu[NE];
__device__ float g_x[NA * HD];
__device__ float g_msg[NA * HD];
__device__ float g_y[NA * HD];
__device__ float g_m[NA * HD];
__device__ float g_tblcf[(size_t)NL * NT * HD];
__device__ float g_tbln[(size_t)NT * HD];

__device__ __forceinline__ float silu_f(float x) {
    return x / (1.0f + __expf(-x));
}

// ---------------- CSR build: pass 1 (count) ----------------
__global__ void geom_count(const int* __restrict__ ei, const float* __restrict__ pos) {
    int e = blockIdx.x * blockDim.x + threadIdx.x;
    if (e >= NE) return;
    int s = ei[e], d = ei[NE + e];
    float dx = pos[3 * s + 0] - pos[3 * d + 0];
    float dy = pos[3 * s + 1] - pos[3 * d + 1];
    float dz = pos[3 * s + 2] - pos[3 * d + 2];
    float d2 = dx * dx + dy * dy + dz * dz + 1e-12f;
    if (d2 < CUTR * CUTR) atomicAdd(&g_cnt[d], 1);
}

// ---------------- scan: exclusive prefix over g_cnt ----------------
__global__ void scan_kernel() {
    __shared__ int sh[1024];
    int tid = threadIdx.x;
    int base = tid * 10;
    int loc[10];
    int sum = 0;
    #pragma unroll
    for (int k = 0; k < 10; k++) {
        int i = base + k;
        int c = (i < NA) ? g_cnt[i] : 0;
        loc[k] = sum; sum += c;
    }
    sh[tid] = sum;
    __syncthreads();
    for (int off = 1; off < 1024; off <<= 1) {
        int v = 0;
        if (tid >= off) v = sh[tid - off];
        __syncthreads();
        sh[tid] += v;
        __syncthreads();
    }
    int pre = (tid == 0) ? 0 : sh[tid - 1];
    #pragma unroll
    for (int k = 0; k < 10; k++) {
        int i = base + k;
        if (i < NA) { g_off[i] = pre + loc[k]; g_cur[i] = pre + loc[k]; }
    }
    if (tid == 1023) g_off[NA] = sh[1023];
}

// ---------------- CSR build: pass 2 (fill) ----------------
__global__ void geom_fill(const int* __restrict__ ei, const float* __restrict__ pos) {
    int e = blockIdx.x * blockDim.x + threadIdx.x;
    if (e >= NE) return;
    int s = ei[e], d = ei[NE + e];
    float dx = pos[3 * s + 0] - pos[3 * d + 0];
    float dy = pos[3 * s + 1] - pos[3 * d + 1];
    float dz = pos[3 * s + 2] - pos[3 * d + 2];
    float d2 = dx * dx + dy * dy + dz * dz + 1e-12f;
    if (d2 < CUTR * CUTR) {
        float dist = sqrtf(d2);
        int j = atomicAdd(&g_cur[d], 1);
        g_csrc[j] = s;
        g_cu[j] = expf(-dist);
    }
}

// ---------------- table build: CFConv filter tables (6 layers) ----------------
__global__ __launch_bounds__(512, 1)
void build_cf(const float* __restrict__ means, const float* __restrict__ betas,
              const float* __restrict__ W1g, const float* __restrict__ b1g,
              const float* __restrict__ W2g, const float* __restrict__ b2g) {
    extern __shared__ float sh[];
    float* sW1 = sh;                 // 6400
    float* sB1 = sW1 + NR * HD;      // 128
    float* sW2 = sB1 + HD;           // 16384
    float* sB2 = sW2 + HD * HD;      // 128
    float* sMu = sB2 + HD;           // 64
    float* sBe = sMu + 64;           // 64
    float* sBuf = sBe + 64;          // 16 * 1456
    int l = blockIdx.y;
    const float* W1 = W1g + (size_t)l * NR * HD;
    const float* W2 = W2g + (size_t)l * HD * HD;
    int tid = threadIdx.x;
    for (int i = tid; i < NR * HD; i += 512) sW1[i] = W1[i];
    for (int i = tid; i < HD * HD; i += 512) sW2[i] = W2[i];
    if (tid < HD) { sB1[tid] = b1g[l * HD + tid]; sB2[tid] = b2g[l * HD + tid]; }
    if (tid < NR) { sMu[tid] = means[tid]; sBe[tid] = betas[tid]; }
    __syncthreads();
    int warp = tid >> 5, lane = tid & 31;
    float* sEA = sBuf + warp * 1456;
    float* sH1 = sEA + 8 * NR;       // stride 132
    int t0 = (blockIdx.x * 16 + warp) * 8;
    for (int i = lane; i < 8 * NR; i += 32) {
        int e = i / NR, r = i - e * NR;
        float u = UMINF + (float)(t0 + e) * INVTF;
        float d = -logf(u);
        float C = (d < CUTR) ? 0.5f * (cosf(PI_F * d / CUTR) + 1.f) : 0.f;
        float td = u - sMu[r];
        sEA[i] = C * expf(-sBe[r] * td * td);
    }
    __syncwarp();
    float4 acc[8];
    #pragma unroll
    for (int e = 0; e < 8; e++) acc[e] = make_float4(0.f, 0.f, 0.f, 0.f);
    #pragma unroll 2
    for (int r = 0; r < NR; r++) {
        float4 w = *(float4*)&sW1[r * HD + 4 * lane];
        #pragma unroll
        for (int e = 0; e < 8; e++) {
            float a = sEA[e * NR + r];
            acc[e].x = fmaf(a, w.x, acc[e].x);
            acc[e].y = fmaf(a, w.y, acc[e].y);
            acc[e].z = fmaf(a, w.z, acc[e].z);
            acc[e].w = fmaf(a, w.w, acc[e].w);
        }
    }
    float4 b1v = *(float4*)&sB1[4 * lane];
    #pragma unroll
    for (int e = 0; e < 8; e++) {
        int c0 = e * 132 + 4 * lane;
        sH1[c0 + 0] = silu_f(acc[e].x + b1v.x);
        sH1[c0 + 1] = silu_f(acc[e].y + b1v.y);
        sH1[c0 + 2] = silu_f(acc[e].z + b1v.z);
        sH1[c0 + 3] = silu_f(acc[e].w + b1v.w);
        acc[e] = make_float4(0.f, 0.f, 0.f, 0.f);
    }
    __syncwarp();
    #pragma unroll 2
    for (int r = 0; r < HD; r++) {
        float4 w = *(float4*)&sW2[r * HD + 4 * lane];
        #pragma unroll
        for (int e = 0; e < 8; e++) {
            float a = sH1[e * 132 + r];
            acc[e].x = fmaf(a, w.x, acc[e].x);
            acc[e].y = fmaf(a, w.y, acc[e].y);
            acc[e].z = fmaf(a, w.z, acc[e].z);
            acc[e].w = fmaf(a, w.w, acc[e].w);
        }
    }
    float4 b2v = *(float4*)&sB2[4 * lane];
    #pragma unroll
    for (int e = 0; e < 8; e++) {
        int t = t0 + e;
        float u = UMINF + (float)t * INVTF;
        float d = -logf(u);
        float C = (d < CUTR) ? 0.5f * (cosf(PI_F * d / CUTR) + 1.f) : 0.f;
        float4 v;
        v.x = (acc[e].x + b2v.x) * C;
        v.y = (acc[e].y + b2v.y) * C;
        v.z = (acc[e].z + b2v.z) * C;
        v.w = (acc[e].w + b2v.w) * C;
        *(float4*)&g_tblcf[((size_t)l * NT + t) * HD + 4 * lane] = v;
    }
}

// ---------------- table build: NeighborEmbedding filter ----------------
__global__ __launch_bounds__(512, 1)
void build_nbr(const float* __restrict__ means, const float* __restrict__ betas,
               const float* __restrict__ Wg, const float* __restrict__ bg) {
    extern __shared__ float sh[];
    float* sW = sh;                  // 6400
    float* sB = sW + NR * HD;        // 128
    float* sMu = sB + HD;            // 64
    float* sBe = sMu + 64;           // 64
    float* sBuf = sBe + 64;          // 16 * 400
    int tid = threadIdx.x;
    for (int i = tid; i < NR * HD; i += 512) sW[i] = Wg[i];
    if (tid < HD) sB[tid] = bg[tid];
    if (tid < NR) { sMu[tid] = means[tid]; sBe[tid] = betas[tid]; }
    __syncthreads();
    int warp = tid >> 5, lane = tid & 31;
    float* sEA = sBuf + warp * 400;
    int t0 = (blockIdx.x * 16 + warp) * 8;
    for (int i = lane; i < 8 * NR; i += 32) {
        int e = i / NR, r = i - e * NR;
        float u = UMINF + (float)(t0 + e) * INVTF;
        float d = -logf(u);
        float C = (d < CUTR) ? 0.5f * (cosf(PI_F * d / CUTR) + 1.f) : 0.f;
        float td = u - sMu[r];
        sEA[i] = C * expf(-sBe[r] * td * td);
    }
    __syncwarp();
    float4 acc[8];
    #pragma unroll
    for (int e = 0; e < 8; e++) acc[e] = make_float4(0.f, 0.f, 0.f, 0.f);
    #pragma unroll 2
    for (int r = 0; r < NR; r++) {
        float4 w = *(float4*)&sW[r * HD + 4 * lane];
        #pragma unroll
        for (int e = 0; e < 8; e++) {
            float a = sEA[e * NR + r];
            acc[e].x = fmaf(a, w.x, acc[e].x);
            acc[e].y = fmaf(a, w.y, acc[e].y);
            acc[e].z = fmaf(a, w.z, acc[e].z);
            acc[e].w = fmaf(a, w.w, acc[e].w);
        }
    }
    float4 bv = *(float4*)&sB[4 * lane];
    #pragma unroll
    for (int e = 0; e < 8; e++) {
        int t = t0 + e;
        float u = UMINF + (float)t * INVTF;
        float d = -logf(u);
        float C = (d < CUTR) ? 0.5f * (cosf(PI_F * d / CUTR) + 1.f) : 0.f;
        float4 v;
        v.x = (acc[e].x + bv.x) * C;
        v.y = (acc[e].y + bv.y) * C;
        v.z = (acc[e].z + bv.z) * C;
        v.w = (acc[e].w + bv.w) * C;
        *(float4*)&g_tbln[(size_t)t * HD + 4 * lane] = v;
    }
}

// ---------------- embeddings ----------------
__global__ void embed2_kernel(const int* __restrict__ z, const float* __restrict__ emb,
                              const float* __restrict__ nemb) {
    int idx = blockIdx.x * blockDim.x + threadIdx.x;
    if (idx >= NA * HD) return;
    int i = idx >> 7, h = idx & 127;
    int zz = z[i];
    g_x[idx] = emb[(size_t)zz * HD + h];
    g_y[idx] = nemb[(size_t)zz * HD + h];
}

// ---------------- edge aggregation via CSR + table lerp ----------------
__device__ __forceinline__ void edge_acc(int j, int n, int lane, int self_mask,
                                         const float* __restrict__ TBL,
                                         const float* __restrict__ Y, float4& acc) {
    int s = __ldg(&g_csrc[j]);
    float u = __ldg(&g_cu[j]);
    float tf = (u - UMINF) * SCALEF;
    tf = fminf(fmaxf(tf, 0.f), (float)(NT - 1));
    int ti = (int)tf;
    if (ti > NT - 2) ti = NT - 2;
    float fr = tf - (float)ti;
    const float4* r0 = (const float4*)(TBL + (size_t)ti * HD) + lane;
    float4 w0 = __ldg(r0);
    float4 w1 = __ldg(r0 + HD / 4);
    float4 yv = __ldg((const float4*)(Y + (size_t)s * HD) + lane);
    float g = (self_mask && (s == n)) ? 0.f : 1.f;
    float wx = fmaf(fr, w1.x - w0.x, w0.x) * g;
    float wy = fmaf(fr, w1.y - w0.y, w0.y) * g;
    float wz = fmaf(fr, w1.z - w0.z, w0.z) * g;
    float ww = fmaf(fr, w1.w - w0.w, w0.w) * g;
    acc.x = fmaf(yv.x, wx, acc.x);
    acc.y = fmaf(yv.y, wy, acc.y);
    acc.z = fmaf(yv.z, wz, acc.z);
    acc.w = fmaf(yv.w, ww, acc.w);
}

__global__ __launch_bounds__(512)
void scatter_kernel(const float* __restrict__ TBL, const float* __restrict__ Y,
                    float* __restrict__ M, int self_mask) {
    int warp = threadIdx.x >> 5, lane = threadIdx.x & 31;
    int gw = blockIdx.x * 16 + warp;
    for (int n = gw; n < NA; n += gridDim.x * 16) {
        int beg = __ldg(&g_off[n]), end = __ldg(&g_off[n + 1]);
        float4 a0 = make_float4(0.f, 0.f, 0.f, 0.f);
        float4 a1 = make_float4(0.f, 0.f, 0.f, 0.f);
        int j = beg;
        for (; j + 1 < end; j += 2) {
            edge_acc(j, n, lane, self_mask, TBL, Y, a0);
            edge_acc(j + 1, n, lane, self_mask, TBL, Y, a1);
        }
        if (j < end) edge_acc(j, n, lane, self_mask, TBL, Y, a0);
        a0.x += a1.x; a0.y += a1.y; a0.z += a1.z; a0.w += a1.w;
        *(float4*)(M + (size_t)n * HD + 4 * lane) = a0;
    }
}

// ---------------- combine: x = [x, msg] @ W(256x128) + b ----------------
__global__ __launch_bounds__(256, 1)
void comb_kernel(const float* __restrict__ W, const float* __restrict__ bg) {
    extern __shared__ float sh[];
    float* sW = sh;
    float* sB = sW + 256 * HD;
    float* sXb = sB + HD;
    int tid = threadIdx.x;
    for (int i = tid; i < 256 * HD; i += 256) sW[i] = W[i];
    if (tid < HD) sB[tid] = bg[tid];
    __syncthreads();
    int warp = tid >> 5, lane = tid & 31;
    float* sX = sXb + warp * 1024;
    int gw = blockIdx.x * 8 + warp, nw = gridDim.x * 8;
    for (int n0 = gw * 4; n0 < NA; n0 += nw * 4) {
        __syncwarp();
        for (int i = lane; i < 1024; i += 32) {
            int n = i >> 8, h = i & 255; int node = n0 + n;
            float v = 0.f;
            if (node < NA) v = (h < HD) ? g_x[node * HD + h] : g_msg[node * HD + h - HD];
            sX[i] = v;
        }
        __syncwarp();
        float4 b4 = *(float4*)&sB[4 * lane];
        float4 acc[4];
        #pragma unroll
        for (int n = 0; n < 4; n++) acc[n] = b4;
        #pragma unroll 2
        for (int r = 0; r < 256; r++) {
            float4 w = *(float4*)&sW[r * HD + 4 * lane];
            #pragma unroll
            for (int n = 0; n < 4; n++) {
                float a = sX[n * 256 + r];
                acc[n].x = fmaf(a, w.x, acc[n].x);
                acc[n].y = fmaf(a, w.y, acc[n].y);
                acc[n].z = fmaf(a, w.z, acc[n].z);
                acc[n].w = fmaf(a, w.w, acc[n].w);
            }
        }
        #pragma unroll
        for (int n = 0; n < 4; n++) {
            int node = n0 + n;
            if (node >= NA) break;
            *(float4*)&g_x[node * HD + 4 * lane] = acc[n];
        }
    }
}

// ---------------- node GEMM: out = X @ W (no bias/act) ----------------
__global__ __launch_bounds__(256, 2)
void node_mm128(const float* __restrict__ X, const float* __restrict__ W,
                float* __restrict__ out) {
    extern __shared__ float sh[];
    float* sW = sh;
    float* sXb = sW + HD * HD;
    int tid = threadIdx.x;
    for (int i = tid; i < HD * HD; i += 256) sW[i] = W[i];
    __syncthreads();
    int warp = tid >> 5, lane = tid & 31;
    float* sX = sXb + warp * 512;
    int gw = blockIdx.x * 8 + warp, nw = gridDim.x * 8;
    for (int n0 = gw * 4; n0 < NA; n0 += nw * 4) {
        __syncwarp();
        for (int i = lane; i < 512; i += 32) {
            int n = i >> 7, h = i & 127; int node = n0 + n;
            sX[i] = (node < NA) ? X[node * HD + h] : 0.f;
        }
        __syncwarp();
        float4 acc[4];
        #pragma unroll
        for (int n = 0; n < 4; n++) acc[n] = make_float4(0.f, 0.f, 0.f, 0.f);
        #pragma unroll 2
        for (int r = 0; r < HD; r++) {
            float4 w = *(float4*)&sW[r * HD + 4 * lane];
            #pragma unroll
            for (int n = 0; n < 4; n++) {
                float a = sX[n * HD + r];
                acc[n].x = fmaf(a, w.x, acc[n].x);
                acc[n].y = fmaf(a, w.y, acc[n].y);
                acc[n].z = fmaf(a, w.z, acc[n].z);
                acc[n].w = fmaf(a, w.w, acc[n].w);
            }
        }
        #pragma unroll
        for (int n = 0; n < 4; n++) {
            int node = n0 + n;
            if (node >= NA) break;
            *(float4*)&out[node * HD + 4 * lane] = acc[n];
        }
    }
}

// ---------------- fused: out = X + silu(M@W2+b2)@WL + bL ----------------
__global__ __launch_bounds__(512, 1)
void fused2_kernel(const float* __restrict__ M,
                   const float* __restrict__ W2, const float* __restrict__ b2,
                   const float* __restrict__ WL, const float* __restrict__ bL,
                   const float* __restrict__ X, float* __restrict__ out) {
    extern __shared__ float sh[];
    float* sW2 = sh;                 // 16384
    float* sWL = sW2 + HD * HD;      // 16384
    float* sB2 = sWL + HD * HD;      // 128
    float* sBL = sB2 + HD;           // 128
    float* sS = sBL + HD;            // 16 * 512
    int tid = threadIdx.x;
    for (int i = tid; i < HD * HD; i += 512) { sW2[i] = W2[i]; sWL[i] = WL[i]; }
    if (tid < HD) { sB2[tid] = b2[tid]; sBL[tid] = bL[tid]; }
    __syncthreads();
    int warp = tid >> 5, lane = tid & 31;
    float* sX = sS + warp * 512;
    int gw = blockIdx.x * 16 + warp, nw = gridDim.x * 16;
    float4 b2v = *(float4*)&sB2[4 * lane];
    float4 bLv = *(float4*)&sBL[4 * lane];
    for (int n0 = gw * 4; n0 < NA; n0 += nw * 4) {
        __syncwarp();
        for (int i = lane; i < 512; i += 32) {
            int n = i >> 7, h = i & 127; int node = n0 + n;
            sX[i] = (node < NA) ? M[node * HD + h] : 0.f;
        }
        __syncwarp();
        float4 acc[4];
        #pragma unroll
        for (int n = 0; n < 4; n++) acc[n] = b2v;
        #pragma unroll 2
        for (int r = 0; r < HD; r++) {
            float4 w = *(float4*)&sW2[r * HD + 4 * lane];
            #pragma unroll
            for (int n = 0; n < 4; n++) {
                float a = sX[n * HD + r];
                acc[n].x = fmaf(a, w.x, acc[n].x);
                acc[n].y = fmaf(a, w.y, acc[n].y);
                acc[n].z = fmaf(a, w.z, acc[n].z);
                acc[n].w = fmaf(a, w.w, acc[n].w);
            }
        }
        __syncwarp();
        #pragma unroll
        for (int n = 0; n < 4; n++) {
            int c0 = n * HD + 4 * lane;
            sX[c0 + 0] = silu_f(acc[n].x);
            sX[c0 + 1] = silu_f(acc[n].y);
            sX[c0 + 2] = silu_f(acc[n].z);
            sX[c0 + 3] = silu_f(acc[n].w);
            acc[n] = bLv;
        }
        __syncwarp();
        #pragma unroll 2
        for (int r = 0; r < HD; r++) {
            float4 w = *(float4*)&sWL[r * HD + 4 * lane];
            #pragma unroll
            for (int n = 0; n < 4; n++) {
                float a = sX[n * HD + r];
                acc[n].x = fmaf(a, w.x, acc[n].x);
                acc[n].y = fmaf(a, w.y, acc[n].y);
                acc[n].z = fmaf(a, w.z, acc[n].z);
                acc[n].w = fmaf(a, w.w, acc[n].w);
            }
        }
        #pragma unroll
        for (int n = 0; n < 4; n++) {
            int node = n0 + n;
            if (node >= NA) break;
            float4 xv = *(const float4*)&X[node * HD + 4 * lane];
            float4 v = acc[n];
            v.x += xv.x; v.y += xv.y; v.z += xv.z; v.w += xv.w;
            *(float4*)&out[node * HD + 4 * lane] = v;
        }
    }
}

// ---------------- launcher ----------------
extern "C" void kernel_launch(void* const* d_in, const int* in_sizes, int n_in,
                              void* d_out, int out_size) {
    const int*   z      = (const int*)d_in[0];
    const float* pos    = (const float*)d_in[1];
    const int*   ei     = (const int*)d_in[3];
    const float* emb    = (const float*)d_in[4];
    const float* nemb   = (const float*)d_in[5];
    const float* nprojW = (const float*)d_in[6];
    const float* nprojB = (const float*)d_in[7];
    const float* ncombW = (const float*)d_in[8];
    const float* ncombB = (const float*)d_in[9];
    const float* means  = (const float*)d_in[10];
    const float* betas  = (const float*)d_in[11];
    const float* mlpW1  = (const float*)d_in[12];
    const float* mlpb1  = (const float*)d_in[13];
    const float* mlpW2  = (const float*)d_in[14];
    const float* mlpb2  = (const float*)d_in[15];
    const float* convW1 = (const float*)d_in[16];
    const float* convW2 = (const float*)d_in[17];
    const float* convb2 = (const float*)d_in[18];
    const float* linW   = (const float*)d_in[19];
    const float* linb   = (const float*)d_in[20];
    float* out = (float*)d_out;

    void *p_cnt, *p_x, *p_y, *p_m, *p_msg, *p_tc, *p_tn;
    cudaGetSymbolAddress(&p_cnt, g_cnt);
    cudaGetSymbolAddress(&p_x, g_x);
    cudaGetSymbolAddress(&p_y, g_y);
    cudaGetSymbolAddress(&p_m, g_m);
    cudaGetSymbolAddress(&p_msg, g_msg);
    cudaGetSymbolAddress(&p_tc, g_tblcf);
    cudaGetSymbolAddress(&p_tn, g_tbln);
    float* px = (float*)p_x;
    float* py = (float*)p_y;
    float* pm = (float*)p_m;
    float* pmsg = (float*)p_msg;
    float* ptc = (float*)p_tc;
    float* ptn = (float*)p_tn;

    size_t sh_bc   = (size_t)(NR * HD + HD + HD * HD + HD + 128 + 16 * 1456) * sizeof(float);
    size_t sh_bn   = (size_t)(NR * HD + HD + 128 + 16 * 400) * sizeof(float);
    size_t sh_comb = (size_t)(256 * HD + HD + 8 * 1024) * sizeof(float);
    size_t sh_mm   = (size_t)(HD * HD + 8 * 512) * sizeof(float);
    size_t sh_f2   = (size_t)(2 * HD * HD + 2 * HD + 16 * 512) * sizeof(float);
    cudaFuncSetAttribute(build_cf,      cudaFuncAttributeMaxDynamicSharedMemorySize, (int)sh_bc);
    cudaFuncSetAttribute(build_nbr,     cudaFuncAttributeMaxDynamicSharedMemorySize, (int)sh_bn);
    cudaFuncSetAttribute(comb_kernel,   cudaFuncAttributeMaxDynamicSharedMemorySize, (int)sh_comb);
    cudaFuncSetAttribute(node_mm128,    cudaFuncAttributeMaxDynamicSharedMemorySize, (int)sh_mm);
    cudaFuncSetAttribute(fused2_kernel, cudaFuncAttributeMaxDynamicSharedMemorySize, (int)sh_f2);

    cudaMemsetAsync(p_cnt, 0, NA * sizeof(int));
    geom_count<<<(NE + 255) / 256, 256>>>(ei, pos);
    scan_kernel<<<1, 1024>>>();
    geom_fill<<<(NE + 255) / 256, 256>>>(ei, pos);
    build_nbr<<<32, 512, sh_bn>>>(means, betas, nprojW, nprojB);
    build_cf<<<dim3(32, NL), 512, sh_bc>>>(means, betas, mlpW1, mlpb1, mlpW2, mlpb2);
    embed2_kernel<<<(NA * HD + 255) / 256, 256>>>(z, emb, nemb);
    scatter_kernel<<<(NA + 15) / 16, 512>>>(ptn, py, pmsg, 1);
    comb_kernel<<<148, 256, sh_comb>>>(ncombW, ncombB);

    for (int l = 0; l < NL; l++) {
        node_mm128<<<296, 256, sh_mm>>>(px, convW1 + (size_t)l * HD * HD, py);
        scatter_kernel<<<(NA + 15) / 16, 512>>>(ptc + (size_t)l * NT * HD, py, pm, 0);
        float* dest = (l == NL - 1) ? out : px;
        fused2_kernel<<<148, 512, sh_f2>>>(pm, convW2 + (size_t)l * HD * HD,
                                           convb2 + (size_t)l * HD,
                                           linW + (size_t)l * HD * HD,
                                           linb + (size_t)l * HD, px, dest);
    }
}

// round 3
// speedup vs baseline: 2.6529x; 1.2081x over previous
#include <cuda_runtime.h>

#define NA 10000
#define NE 320000
#define HD 128
#define NR 50
#define NL 6
#define NT 1024
#define CUTR 5.0f
#define PI_F 3.14159265358979f

// u = exp(-d) mapping constants
#define UMINF 0.0067379469990854670966f
#define INVTF ((1.0f - UMINF) / (float)(NT - 1))
#define SCALEF ((float)(NT - 1) / (1.0f - UMINF))

typedef unsigned long long ull;

// ---------------- scratch ----------------
__device__ int   g_cnt[NA];
__device__ int   g_off[NA + 1];
__device__ int   g_cur[NA];
__device__ int   g_csrc[NE];
__device__ float g_cu[NE];
__device__ float g_tmp[NE];
__device__ float g_x[NA * HD];
__device__ float g_msg[NA * HD];
__device__ float g_y[NA * HD];
__device__ float g_m[NA * HD];
__device__ float g_tblcf[(size_t)NL * NT * HD];
__device__ float g_tbln[(size_t)NT * HD];

__device__ __forceinline__ float silu_f(float x) { return x / (1.0f + __expf(-x)); }

__device__ __forceinline__ ull ffma2(ull a, ull b, ull c) {
    ull d;
    asm("fma.rn.f32x2 %0, %1, %2, %3;" : "=l"(d) : "l"(a), "l"(b), "l"(c));
    return d;
}
__device__ __forceinline__ float lo32(ull p) { return __uint_as_float((unsigned)p); }
__device__ __forceinline__ float hi32(ull p) { return __uint_as_float((unsigned)(p >> 32)); }

// ---------------- CSR pass 1: distance + count ----------------
__global__ void geom_count(const int* __restrict__ ei, const float* __restrict__ pos) {
    int e = blockIdx.x * blockDim.x + threadIdx.x;
    if (e >= NE) return;
    int s = ei[e], d = ei[NE + e];
    float dx = pos[3 * s + 0] - pos[3 * d + 0];
    float dy = pos[3 * s + 1] - pos[3 * d + 1];
    float dz = pos[3 * s + 2] - pos[3 * d + 2];
    float d2 = dx * dx + dy * dy + dz * dz + 1e-12f;
    if (d2 < CUTR * CUTR) {
        g_tmp[e] = expf(-sqrtf(d2));
        atomicAdd(&g_cnt[d], 1);
    } else {
        g_tmp[e] = -1.f;
    }
}

// ---------------- scan ----------------
__global__ void scan_kernel() {
    __shared__ int sh[1024];
    int tid = threadIdx.x;
    int base = tid * 10;
    int loc[10];
    int sum = 0;
    #pragma unroll
    for (int k = 0; k < 10; k++) {
        int i = base + k;
        int c = (i < NA) ? g_cnt[i] : 0;
        loc[k] = sum; sum += c;
    }
    sh[tid] = sum;
    __syncthreads();
    for (int off = 1; off < 1024; off <<= 1) {
        int v = 0;
        if (tid >= off) v = sh[tid - off];
        __syncthreads();
        sh[tid] += v;
        __syncthreads();
    }
    int pre = (tid == 0) ? 0 : sh[tid - 1];
    #pragma unroll
    for (int k = 0; k < 10; k++) {
        int i = base + k;
        if (i < NA) { g_off[i] = pre + loc[k]; g_cur[i] = pre + loc[k]; }
    }
    if (tid == 1023) g_off[NA] = sh[1023];
}

// ---------------- CSR pass 2: fill ----------------
__global__ void geom_fill(const int* __restrict__ ei) {
    int e = blockIdx.x * blockDim.x + threadIdx.x;
    if (e >= NE) return;
    float u = g_tmp[e];
    if (u >= 0.f) {
        int d = ei[NE + e];
        int j = atomicAdd(&g_cur[d], 1);
        g_csrc[j] = ei[e];
        g_cu[j] = u;
    }
}

// ---------------- table build: CFConv (2 rows/warp) ----------------
__global__ __launch_bounds__(512, 1)
void build_cf(const float* __restrict__ means, const float* __restrict__ betas,
              const float* __restrict__ W1g, const float* __restrict__ b1g,
              const float* __restrict__ W2g, const float* __restrict__ b2g) {
    extern __shared__ float sh[];
    float* sW1 = sh;                 // 6400
    float* sB1 = sW1 + NR * HD;      // 128
    float* sW2 = sB1 + HD;           // 16384
    float* sB2 = sW2 + HD * HD;      // 128
    float* sMu = sB2 + HD;           // 64
    float* sBe = sMu + 64;           // 64
    float* sBuf = sBe + 64;          // 16 * 364
    int l = blockIdx.y;
    const float* W1 = W1g + (size_t)l * NR * HD;
    const float* W2 = W2g + (size_t)l * HD * HD;
    int tid = threadIdx.x;
    for (int i = tid; i < NR * HD; i += 512) sW1[i] = W1[i];
    for (int i = tid; i < HD * HD; i += 512) sW2[i] = W2[i];
    if (tid < HD) { sB1[tid] = b1g[l * HD + tid]; sB2[tid] = b2g[l * HD + tid]; }
    if (tid < NR) { sMu[tid] = means[tid]; sBe[tid] = betas[tid]; }
    __syncthreads();
    int warp = tid >> 5, lane = tid & 31;
    float* sEA = sBuf + warp * 364;
    float* sH1 = sEA + 2 * NR;       // stride 132
    int t0 = (blockIdx.x * 16 + warp) * 2;
    for (int i = lane; i < 2 * NR; i += 32) {
        int e = i / NR, r = i - e * NR;
        float u = UMINF + (float)(t0 + e) * INVTF;
        float d = -logf(u);
        float C = (d < CUTR) ? 0.5f * (cosf(PI_F * d / CUTR) + 1.f) : 0.f;
        float td = u - sMu[r];
        sEA[i] = C * expf(-sBe[r] * td * td);
    }
    __syncwarp();
    float4 acc[2];
    #pragma unroll
    for (int e = 0; e < 2; e++) acc[e] = make_float4(0.f, 0.f, 0.f, 0.f);
    #pragma unroll 2
    for (int r = 0; r < NR; r++) {
        float4 w = *(float4*)&sW1[r * HD + 4 * lane];
        #pragma unroll
        for (int e = 0; e < 2; e++) {
            float a = sEA[e * NR + r];
            acc[e].x = fmaf(a, w.x, acc[e].x);
            acc[e].y = fmaf(a, w.y, acc[e].y);
            acc[e].z = fmaf(a, w.z, acc[e].z);
            acc[e].w = fmaf(a, w.w, acc[e].w);
        }
    }
    float4 b1v = *(float4*)&sB1[4 * lane];
    #pragma unroll
    for (int e = 0; e < 2; e++) {
        int c0 = e * 132 + 4 * lane;
        sH1[c0 + 0] = silu_f(acc[e].x + b1v.x);
        sH1[c0 + 1] = silu_f(acc[e].y + b1v.y);
        sH1[c0 + 2] = silu_f(acc[e].z + b1v.z);
        sH1[c0 + 3] = silu_f(acc[e].w + b1v.w);
        acc[e] = make_float4(0.f, 0.f, 0.f, 0.f);
    }
    __syncwarp();
    #pragma unroll 2
    for (int r = 0; r < HD; r++) {
        float4 w = *(float4*)&sW2[r * HD + 4 * lane];
        #pragma unroll
        for (int e = 0; e < 2; e++) {
            float a = sH1[e * 132 + r];
            acc[e].x = fmaf(a, w.x, acc[e].x);
            acc[e].y = fmaf(a, w.y, acc[e].y);
            acc[e].z = fmaf(a, w.z, acc[e].z);
            acc[e].w = fmaf(a, w.w, acc[e].w);
        }
    }
    float4 b2v = *(float4*)&sB2[4 * lane];
    #pragma unroll
    for (int e = 0; e < 2; e++) {
        int t = t0 + e;
        float u = UMINF + (float)t * INVTF;
        float d = -logf(u);
        float C = (d < CUTR) ? 0.5f * (cosf(PI_F * d / CUTR) + 1.f) : 0.f;
        float4 v;
        v.x = (acc[e].x + b2v.x) * C;
        v.y = (acc[e].y + b2v.y) * C;
        v.z = (acc[e].z + b2v.z) * C;
        v.w = (acc[e].w + b2v.w) * C;
        *(float4*)&g_tblcf[((size_t)l * NT + t) * HD + 4 * lane] = v;
    }
}

// ---------------- table build: NeighborEmbedding (1 row/warp) ----------------
__global__ __launch_bounds__(512, 1)
void build_nbr(const float* __restrict__ means, const float* __restrict__ betas,
               const float* __restrict__ Wg, const float* __restrict__ bg) {
    extern __shared__ float sh[];
    float* sW = sh;                  // 6400
    float* sB = sW + NR * HD;        // 128
    float* sMu = sB + HD;            // 64
    float* sBe = sMu + 64;           // 64
    float* sBuf = sBe + 64;          // 16 * NR
    int tid = threadIdx.x;
    for (int i = tid; i < NR * HD; i += 512) sW[i] = Wg[i];
    if (tid < HD) sB[tid] = bg[tid];
    if (tid < NR) { sMu[tid] = means[tid]; sBe[tid] = betas[tid]; }
    __syncthreads();
    int warp = tid >> 5, lane = tid & 31;
    float* sEA = sBuf + warp * NR;
    int t = blockIdx.x * 16 + warp;
    float u = UMINF + (float)t * INVTF;
    float d = -logf(u);
    float C = (d < CUTR) ? 0.5f * (cosf(PI_F * d / CUTR) + 1.f) : 0.f;
    for (int r = lane; r < NR; r += 32) {
        float td = u - sMu[r];
        sEA[r] = C * expf(-sBe[r] * td * td);
    }
    __syncwarp();
    float4 acc = make_float4(0.f, 0.f, 0.f, 0.f);
    #pragma unroll 2
    for (int r = 0; r < NR; r++) {
        float4 w = *(float4*)&sW[r * HD + 4 * lane];
        float a = sEA[r];
        acc.x = fmaf(a, w.x, acc.x);
        acc.y = fmaf(a, w.y, acc.y);
        acc.z = fmaf(a, w.z, acc.z);
        acc.w = fmaf(a, w.w, acc.w);
    }
    float4 bv = *(float4*)&sB[4 * lane];
    float4 v;
    v.x = (acc.x + bv.x) * C;
    v.y = (acc.y + bv.y) * C;
    v.z = (acc.z + bv.z) * C;
    v.w = (acc.w + bv.w) * C;
    *(float4*)&g_tbln[(size_t)t * HD + 4 * lane] = v;
}

// ---------------- embeddings ----------------
__global__ void embed2_kernel(const int* __restrict__ z, const float* __restrict__ emb,
                              const float* __restrict__ nemb) {
    int idx = blockIdx.x * blockDim.x + threadIdx.x;
    if (idx >= NA * HD) return;
    int i = idx >> 7, h = idx & 127;
    int zz = z[i];
    g_x[idx] = emb[(size_t)zz * HD + h];
    g_y[idx] = nemb[(size_t)zz * HD + h];
}

// ---------------- scatter: per-dst aggregation via table lerp ----------------
__device__ __forceinline__ void edge_acc(int j, int n, int lane, int self_mask,
                                         const float* __restrict__ TBL,
                                         const float* __restrict__ Y, float4& acc) {
    int s = __ldg(&g_csrc[j]);
    float u = __ldg(&g_cu[j]);
    float tf = (u - UMINF) * SCALEF;
    tf = fminf(fmaxf(tf, 0.f), (float)(NT - 1));
    int ti = (int)tf;
    if (ti > NT - 2) ti = NT - 2;
    float fr = tf - (float)ti;
    const float4* r0 = (const float4*)(TBL + (size_t)ti * HD) + lane;
    float4 w0 = __ldg(r0);
    float4 w1 = __ldg(r0 + HD / 4);
    float4 yv = __ldg((const float4*)(Y + (size_t)s * HD) + lane);
    float g = (self_mask && (s == n)) ? 0.f : 1.f;
    float wx = fmaf(fr, w1.x - w0.x, w0.x) * g;
    float wy = fmaf(fr, w1.y - w0.y, w0.y) * g;
    float wz = fmaf(fr, w1.z - w0.z, w0.z) * g;
    float ww = fmaf(fr, w1.w - w0.w, w0.w) * g;
    acc.x = fmaf(yv.x, wx, acc.x);
    acc.y = fmaf(yv.y, wy, acc.y);
    acc.z = fmaf(yv.z, wz, acc.z);
    acc.w = fmaf(yv.w, ww, acc.w);
}

__global__ __launch_bounds__(512)
void scatter_kernel(const float* __restrict__ TBL, const float* __restrict__ Y,
                    float* __restrict__ M, int self_mask) {
    int warp = threadIdx.x >> 5, lane = threadIdx.x & 31;
    int gw = blockIdx.x * 16 + warp;
    for (int n = gw; n < NA; n += gridDim.x * 16) {
        int beg = __ldg(&g_off[n]), end = __ldg(&g_off[n + 1]);
        float4 a0 = make_float4(0.f, 0.f, 0.f, 0.f);
        float4 a1 = make_float4(0.f, 0.f, 0.f, 0.f);
        int j = beg;
        for (; j + 1 < end; j += 2) {
            edge_acc(j, n, lane, self_mask, TBL, Y, a0);
            edge_acc(j + 1, n, lane, self_mask, TBL, Y, a1);
        }
        if (j < end) edge_acc(j, n, lane, self_mask, TBL, Y, a0);
        a0.x += a1.x; a0.y += a1.y; a0.z += a1.z; a0.w += a1.w;
        *(float4*)(M + (size_t)n * HD + 4 * lane) = a0;
    }
}

// ---------------- comb (f32x2): x = [x,msg] @ W(256x128) + b ----------------
__global__ __launch_bounds__(256, 1)
void comb_f2(const float* __restrict__ W, const float* __restrict__ bg) {
    extern __shared__ float sh[];
    float* sW = sh;                  // 256*HD
    float* sB = sW + 256 * HD;       // HD
    float* sD = sB + HD;             // 8 warps * 2048 (4 nodes * 512 dup)
    int tid = threadIdx.x;
    const float4* Wv = (const float4*)W;
    for (int i = tid; i < 256 * HD / 4; i += 256) ((float4*)sW)[i] = Wv[i];
    if (tid < HD) sB[tid] = bg[tid];
    __syncthreads();
    int warp = tid >> 5, lane = tid & 31;
    float* sX = sD + warp * 2048;
    int gw = blockIdx.x * 8 + warp, nw = gridDim.x * 8;
    ull b01 = *(ull*)&sB[4 * lane];
    ull b23 = *(ull*)&sB[4 * lane + 2];
    for (int n0 = gw * 4; n0 < NA; n0 += nw * 4) {
        __syncwarp();
        for (int i = lane; i < 1024; i += 32) {
            int n = i >> 8, h = i & 255; int node = n0 + n;
            float v = 0.f;
            if (node < NA) v = (h < HD) ? g_x[node * HD + h] : g_msg[node * HD + h - HD];
            *(float2*)&sX[n * 512 + 2 * h] = make_float2(v, v);
        }
        __syncwarp();
        ull acc[4][2];
        #pragma unroll
        for (int n = 0; n < 4; n++) { acc[n][0] = b01; acc[n][1] = b23; }
        #pragma unroll 2
        for (int r = 0; r < 256; r++) {
            ulonglong2 w = *(ulonglong2*)&sW[r * HD + 4 * lane];
            #pragma unroll
            for (int n = 0; n < 4; n++) {
                ull a = *(ull*)&sX[n * 512 + 2 * r];
                acc[n][0] = ffma2(a, w.x, acc[n][0]);
                acc[n][1] = ffma2(a, w.y, acc[n][1]);
            }
        }
        #pragma unroll
        for (int n = 0; n < 4; n++) {
            int node = n0 + n;
            if (node >= NA) break;
            *(float4*)&g_x[node * HD + 4 * lane] =
                make_float4(lo32(acc[n][0]), hi32(acc[n][0]), lo32(acc[n][1]), hi32(acc[n][1]));
        }
    }
}

// ---------------- mm (f32x2): y = x @ W (no bias) ----------------
__global__ __launch_bounds__(256, 2)
void mm_f2(const float* __restrict__ X, const float* __restrict__ W,
           float* __restrict__ out) {
    extern __shared__ float sh[];
    float* sW = sh;                  // HD*HD
    float* sD = sW + HD * HD;        // 8 warps * 1024
    int tid = threadIdx.x;
    const float4* Wv = (const float4*)W;
    for (int i = tid; i < HD * HD / 4; i += 256) ((float4*)sW)[i] = Wv[i];
    __syncthreads();
    int warp = tid >> 5, lane = tid & 31;
    float* sX = sD + warp * 1024;
    int gw = blockIdx.x * 8 + warp, nw = gridDim.x * 8;
    for (int n0 = gw * 4; n0 < NA; n0 += nw * 4) {
        __syncwarp();
        for (int i = lane; i < 512; i += 32) {
            int n = i >> 7, h = i & 127; int node = n0 + n;
            float v = (node < NA) ? X[node * HD + h] : 0.f;
            *(float2*)&sX[n * 256 + 2 * h] = make_float2(v, v);
        }
        __syncwarp();
        ull acc[4][2] = {};
        #pragma unroll 2
        for (int r = 0; r < HD; r++) {
            ulonglong2 w = *(ulonglong2*)&sW[r * HD + 4 * lane];
            #pragma unroll
            for (int n = 0; n < 4; n++) {
                ull a = *(ull*)&sX[n * 256 + 2 * r];
                acc[n][0] = ffma2(a, w.x, acc[n][0]);
                acc[n][1] = ffma2(a, w.y, acc[n][1]);
            }
        }
        #pragma unroll
        for (int n = 0; n < 4; n++) {
            int node = n0 + n;
            if (node >= NA) break;
            *(float4*)&out[node * HD + 4 * lane] =
                make_float4(lo32(acc[n][0]), hi32(acc[n][0]), lo32(acc[n][1]), hi32(acc[n][1]));
        }
    }
}

// ------- fused3 (f32x2): t=silu(M@W2+b2); xn=X+t@WL+bL -> xout; y=xn@W1n -> yout -------
__global__ __launch_bounds__(256, 1)
void fused3_kernel(const float* __restrict__ M,
                   const float* __restrict__ W2, const float* __restrict__ b2,
                   const float* __restrict__ WL, const float* __restrict__ bL,
                   const float* __restrict__ W1n,
                   const float* __restrict__ X,
                   float* __restrict__ xout, float* __restrict__ yout) {
    extern __shared__ float sh[];
    float* sW2 = sh;                  // 16384
    float* sWL = sW2 + HD * HD;       // 16384
    float* sW1 = sWL + HD * HD;       // 16384
    float* sB  = sW1 + HD * HD;       // 256
    float* sD  = sB + 256;            // 8 warps * 1024
    int tid = threadIdx.x;
    for (int i = tid; i < HD * HD / 4; i += 256) {
        ((float4*)sW2)[i] = ((const float4*)W2)[i];
        ((float4*)sWL)[i] = ((const float4*)WL)[i];
        if (W1n) ((float4*)sW1)[i] = ((const float4*)W1n)[i];
    }
    if (tid < HD) { sB[tid] = b2[tid]; sB[HD + tid] = bL[tid]; }
    __syncthreads();
    int warp = tid >> 5, lane = tid & 31;
    float* sX = sD + warp * 1024;
    int gw = blockIdx.x * 8 + warp, nw = gridDim.x * 8;
    ull b2a = *(ull*)&sB[4 * lane];
    ull b2b = *(ull*)&sB[4 * lane + 2];
    ull bLa = *(ull*)&sB[HD + 4 * lane];
    ull bLb = *(ull*)&sB[HD + 4 * lane + 2];
    for (int n0 = gw * 4; n0 < NA; n0 += nw * 4) {
        __syncwarp();
        // stage 1 input: M rows, duplicated
        for (int i = lane; i < 512; i += 32) {
            int n = i >> 7, h = i & 127; int node = n0 + n;
            float v = (node < NA) ? M[node * HD + h] : 0.f;
            *(float2*)&sX[n * 256 + 2 * h] = make_float2(v, v);
        }
        __syncwarp();
        ull acc[4][2];
        #pragma unroll
        for (int n = 0; n < 4; n++) { acc[n][0] = b2a; acc[n][1] = b2b; }
        #pragma unroll 2
        for (int r = 0; r < HD; r++) {
            ulonglong2 w = *(ulonglong2*)&sW2[r * HD + 4 * lane];
            #pragma unroll
            for (int n = 0; n < 4; n++) {
                ull a = *(ull*)&sX[n * 256 + 2 * r];
                acc[n][0] = ffma2(a, w.x, acc[n][0]);
                acc[n][1] = ffma2(a, w.y, acc[n][1]);
            }
        }
        __syncwarp();
        // silu -> dup buffer
        #pragma unroll
        for (int n = 0; n < 4; n++) {
            int c0 = n * 256 + 8 * lane;
            float t0 = silu_f(lo32(acc[n][0])), t1 = silu_f(hi32(acc[n][0]));
            float t2 = silu_f(lo32(acc[n][1])), t3 = silu_f(hi32(acc[n][1]));
            *(float2*)&sX[c0 + 0] = make_float2(t0, t0);
            *(float2*)&sX[c0 + 2] = make_float2(t1, t1);
            *(float2*)&sX[c0 + 4] = make_float2(t2, t2);
            *(float2*)&sX[c0 + 6] = make_float2(t3, t3);
            acc[n][0] = bLa; acc[n][1] = bLb;
        }
        __syncwarp();
        // stage 2: t @ WL + bL
        #pragma unroll 2
        for (int r = 0; r < HD; r++) {
            ulonglong2 w = *(ulonglong2*)&sWL[r * HD + 4 * lane];
            #pragma unroll
            for (int n = 0; n < 4; n++) {
                ull a = *(ull*)&sX[n * 256 + 2 * r];
                acc[n][0] = ffma2(a, w.x, acc[n][0]);
                acc[n][1] = ffma2(a, w.y, acc[n][1]);
            }
        }
        __syncwarp();
        // residual + store x_new (+ dup for stage 3)
        float4 xn[4];
        #pragma unroll
        for (int n = 0; n < 4; n++) {
            int node = n0 + n;
            if (node >= NA) { xn[n] = make_float4(0.f, 0.f, 0.f, 0.f); continue; }
            float4 xv = *(const float4*)&X[node * HD + 4 * lane];
            xn[n].x = xv.x + lo32(acc[n][0]);
            xn[n].y = xv.y + hi32(acc[n][0]);
            xn[n].z = xv.z + lo32(acc[n][1]);
            xn[n].w = xv.w + hi32(acc[n][1]);
            *(float4*)&xout[node * HD + 4 * lane] = xn[n];
        }
        if (W1n) {
            #pragma unroll
            for (int n = 0; n < 4; n++) {
                int c0 = n * 256 + 8 * lane;
                *(float2*)&sX[c0 + 0] = make_float2(xn[n].x, xn[n].x);
                *(float2*)&sX[c0 + 2] = make_float2(xn[n].y, xn[n].y);
                *(float2*)&sX[c0 + 4] = make_float2(xn[n].z, xn[n].z);
                *(float2*)&sX[c0 + 6] = make_float2(xn[n].w, xn[n].w);
                acc[n][0] = 0ull; acc[n][1] = 0ull;
            }
            __syncwarp();
            // stage 3: y_next = x_new @ W1n
            #pragma unroll 2
            for (int r = 0; r < HD; r++) {
                ulonglong2 w = *(ulonglong2*)&sW1[r * HD + 4 * lane];
                #pragma unroll
                for (int n = 0; n < 4; n++) {
                    ull a = *(ull*)&sX[n * 256 + 2 * r];
                    acc[n][0] = ffma2(a, w.x, acc[n][0]);
                    acc[n][1] = ffma2(a, w.y, acc[n][1]);
                }
            }
            #pragma unroll
            for (int n = 0; n < 4; n++) {
                int node = n0 + n;
                if (node >= NA) break;
                *(float4*)&yout[node * HD + 4 * lane] =
                    make_float4(lo32(acc[n][0]), hi32(acc[n][0]), lo32(acc[n][1]), hi32(acc[n][1]));
            }
        }
    }
}

// ---------------- launcher ----------------
extern "C" void kernel_launch(void* const* d_in, const int* in_sizes, int n_in,
                              void* d_out, int out_size) {
    const int*   z      = (const int*)d_in[0];
    const float* pos    = (const float*)d_in[1];
    const int*   ei     = (const int*)d_in[3];
    const float* emb    = (const float*)d_in[4];
    const float* nemb   = (const float*)d_in[5];
    const float* nprojW = (const float*)d_in[6];
    const float* nprojB = (const float*)d_in[7];
    const float* ncombW = (const float*)d_in[8];
    const float* ncombB = (const float*)d_in[9];
    const float* means  = (const float*)d_in[10];
    const float* betas  = (const float*)d_in[11];
    const float* mlpW1  = (const float*)d_in[12];
    const float* mlpb1  = (const float*)d_in[13];
    const float* mlpW2  = (const float*)d_in[14];
    const float* mlpb2  = (const float*)d_in[15];
    const float* convW1 = (const float*)d_in[16];
    const float* convW2 = (const float*)d_in[17];
    const float* convb2 = (const float*)d_in[18];
    const float* linW   = (const float*)d_in[19];
    const float* linb   = (const float*)d_in[20];
    float* out = (float*)d_out;

    void *p_cnt, *p_x, *p_y, *p_m, *p_msg, *p_tc, *p_tn;
    cudaGetSymbolAddress(&p_cnt, g_cnt);
    cudaGetSymbolAddress(&p_x, g_x);
    cudaGetSymbolAddress(&p_y, g_y);
    cudaGetSymbolAddress(&p_m, g_m);
    cudaGetSymbolAddress(&p_msg, g_msg);
    cudaGetSymbolAddress(&p_tc, g_tblcf);
    cudaGetSymbolAddress(&p_tn, g_tbln);
    float* px = (float*)p_x;
    float* py = (float*)p_y;
    float* pm = (float*)p_m;
    float* pmsg = (float*)p_msg;
    float* ptc = (float*)p_tc;
    float* ptn = (float*)p_tn;

    size_t sh_bc   = (size_t)(NR * HD + HD + HD * HD + HD + 128 + 16 * 364) * sizeof(float);
    size_t sh_bn   = (size_t)(NR * HD + HD + 128 + 16 * NR) * sizeof(float);
    size_t sh_comb = (size_t)(256 * HD + HD + 8 * 2048) * sizeof(float);
    size_t sh_mm   = (size_t)(HD * HD + 8 * 1024) * sizeof(float);
    size_t sh_f3   = (size_t)(3 * HD * HD + 256 + 8 * 1024) * sizeof(float);
    cudaFuncSetAttribute(build_cf,      cudaFuncAttributeMaxDynamicSharedMemorySize, (int)sh_bc);
    cudaFuncSetAttribute(build_nbr,     cudaFuncAttributeMaxDynamicSharedMemorySize, (int)sh_bn);
    cudaFuncSetAttribute(comb_f2,       cudaFuncAttributeMaxDynamicSharedMemorySize, (int)sh_comb);
    cudaFuncSetAttribute(mm_f2,         cudaFuncAttributeMaxDynamicSharedMemorySize, (int)sh_mm);
    cudaFuncSetAttribute(fused3_kernel, cudaFuncAttributeMaxDynamicSharedMemorySize, (int)sh_f3);

    cudaMemsetAsync(p_cnt, 0, NA * sizeof(int));
    geom_count<<<(NE + 255) / 256, 256>>>(ei, pos);
    scan_kernel<<<1, 1024>>>();
    geom_fill<<<(NE + 255) / 256, 256>>>(ei);
    build_nbr<<<NT / 16, 512, sh_bn>>>(means, betas, nprojW, nprojB);
    build_cf<<<dim3(NT / 32, NL), 512, sh_bc>>>(means, betas, mlpW1, mlpb1, mlpW2, mlpb2);
    embed2_kernel<<<(NA * HD + 255) / 256, 256>>>(z, emb, nemb);
    scatter_kernel<<<(NA + 15) / 16, 512>>>(ptn, py, pmsg, 1);
    comb_f2<<<148, 256, sh_comb>>>(ncombW, ncombB);
    mm_f2<<<296, 256, sh_mm>>>(px, convW1, py);   // y0 = x @ convW1[0]

    for (int l = 0; l < NL; l++) {
        scatter_kernel<<<(NA + 15) / 16, 512>>>(ptc + (size_t)l * NT * HD, py, pm, 0);
        float* dest = (l == NL - 1) ? out : px;
        const float* W1n = (l == NL - 1) ? nullptr : (convW1 + (size_t)(l + 1) * HD * HD);
        fused3_kernel<<<148, 256, sh_f3>>>(pm, convW2 + (size_t)l * HD * HD,
                                           convb2 + (size_t)l * HD,
                                           linW + (size_t)l * HD * HD,
                                           linb + (size_t)l * HD,
                                           W1n, px, dest, py);
    }
}

// round 4
// speedup vs baseline: 3.2172x; 1.2127x over previous
#include <cuda_runtime.h>
#include <cuda_fp16.h>

#define NA 10000
#define NE 320000
#define HD 128
#define NR 50
#define NL 6
#define NT 1024
#define CUTR 5.0f
#define PI_F 3.14159265358979f

#define UMINF 0.0067379469990854670966f
#define INVTF ((1.0f - UMINF) / (float)(NT - 1))
#define SCALEF ((float)(NT - 1) / (1.0f - UMINF))

#define F3W 7     // warps per block in fused kernels
#define F3N 10    // nodes per warp in fused3
#define CMN 5     // nodes per warp-pass in comb_mm
#define NBLK 148

typedef unsigned long long ull;

// ---------------- scratch ----------------
__device__ int    g_cnt[NA];
__device__ int    g_off[NA + 1];
__device__ int    g_cur[NA];
__device__ int2   g_edge[NE];             // (src, u_bits)
__device__ float  g_tmp[NE];
__device__ float  g_x[NA * HD];
__device__ float  g_msg[NA * HD];
__device__ __half g_yh[NA * HD];
__device__ float  g_m[NA * HD];
__device__ __half g_tblcf_h[(size_t)NL * NT * HD];
__device__ __half g_tbln_h[(size_t)NT * HD];

__device__ __forceinline__ float silu_f(float x) { return x / (1.0f + __expf(-x)); }

__device__ __forceinline__ ull ffma2(ull a, ull b, ull c) {
    ull d;
    asm("fma.rn.f32x2 %0, %1, %2, %3;" : "=l"(d) : "l"(a), "l"(b), "l"(c));
    return d;
}
__device__ __forceinline__ ull dup2(float a) {
    unsigned u = __float_as_uint(a);
    ull r;
    asm("mov.b64 %0, {%1, %1};" : "=l"(r) : "r"(u));
    return r;
}
__device__ __forceinline__ ull pack2(float a, float b) {
    unsigned ua = __float_as_uint(a), ub = __float_as_uint(b);
    ull r;
    asm("mov.b64 %0, {%1, %2};" : "=l"(r) : "r"(ua), "r"(ub));
    return r;
}
__device__ __forceinline__ float lo32(ull p) { return __uint_as_float((unsigned)p); }
__device__ __forceinline__ float hi32(ull p) { return __uint_as_float((unsigned)(p >> 32)); }

// ================= MEGA SETUP =================
// block ranges: [0,625) geom_count | [625,825) embed | [825,889) build_nbr | [889,1081) build_cf
__global__ __launch_bounds__(512, 2)
void mega_setup(const int* __restrict__ ei, const float* __restrict__ pos,
                const int* __restrict__ z, const float* __restrict__ emb,
                const float* __restrict__ nemb,
                const float* __restrict__ means, const float* __restrict__ betas,
                const float* __restrict__ nprojW, const float* __restrict__ nprojB,
                const float* __restrict__ mlpW1, const float* __restrict__ mlpb1,
                const float* __restrict__ mlpW2, const float* __restrict__ mlpb2) {
    extern __shared__ float sh[];
    int b = blockIdx.x;
    int tid = threadIdx.x;
    if (b < 625) {
        // ---- geom_count ----
        int e = b * 512 + tid;
        if (e >= NE) return;
        int s = ei[e], d = ei[NE + e];
        float dx = pos[3 * s + 0] - pos[3 * d + 0];
        float dy = pos[3 * s + 1] - pos[3 * d + 1];
        float dz = pos[3 * s + 2] - pos[3 * d + 2];
        float d2 = dx * dx + dy * dy + dz * dz + 1e-12f;
        if (d2 < CUTR * CUTR) {
            g_tmp[e] = expf(-sqrtf(d2));
            atomicAdd(&g_cnt[d], 1);
        } else {
            g_tmp[e] = -1.f;
        }
    } else if (b < 825) {
        // ---- embed: x (f32) + y0 source (fp16) ----
        for (int idx = (b - 625) * 512 + tid; idx < NA * HD; idx += 200 * 512) {
            int i = idx >> 7, h = idx & 127;
            int zz = z[i];
            g_x[idx] = emb[(size_t)zz * HD + h];
            g_yh[idx] = __float2half(nemb[(size_t)zz * HD + h]);
        }
    } else if (b < 889) {
        // ---- build_nbr: 16 warps, 1 table row each ----
        float* sW = sh;                  // 6400
        float* sB = sW + NR * HD;        // 128
        float* sMu = sB + HD;            // 64
        float* sBe = sMu + 64;           // 64
        float* sBuf = sBe + 64;          // 16 * NR
        for (int i = tid; i < NR * HD; i += 512) sW[i] = nprojW[i];
        if (tid < HD) sB[tid] = nprojB[tid];
        if (tid < NR) { sMu[tid] = means[tid]; sBe[tid] = betas[tid]; }
        __syncthreads();
        int warp = tid >> 5, lane = tid & 31;
        float* sEA = sBuf + warp * NR;
        int t = (b - 825) * 16 + warp;
        float u = UMINF + (float)t * INVTF;
        float d = -logf(u);
        float C = (d < CUTR) ? 0.5f * (cosf(PI_F * d / CUTR) + 1.f) : 0.f;
        for (int r = lane; r < NR; r += 32) {
            float td = u - sMu[r];
            sEA[r] = C * expf(-sBe[r] * td * td);
        }
        __syncwarp();
        float4 acc = make_float4(0.f, 0.f, 0.f, 0.f);
        #pragma unroll 2
        for (int r = 0; r < NR; r++) {
            float4 w = *(float4*)&sW[r * HD + 4 * lane];
            float a = sEA[r];
            acc.x = fmaf(a, w.x, acc.x);
            acc.y = fmaf(a, w.y, acc.y);
            acc.z = fmaf(a, w.z, acc.z);
            acc.w = fmaf(a, w.w, acc.w);
        }
        float4 bv = *(float4*)&sB[4 * lane];
        __half2* p = (__half2*)&g_tbln_h[(size_t)t * HD + 4 * lane];
        p[0] = __floats2half2_rn((acc.x + bv.x) * C, (acc.y + bv.y) * C);
        p[1] = __floats2half2_rn((acc.z + bv.z) * C, (acc.w + bv.w) * C);
    } else {
        // ---- build_cf: 6 layers x 32 blocks, 16 warps x 2 rows ----
        int bb = b - 889;
        int l = bb >> 5;
        int blk = bb & 31;
        float* sW1 = sh;                 // 6400
        float* sB1 = sW1 + NR * HD;      // 128
        float* sW2 = sB1 + HD;           // 16384
        float* sB2 = sW2 + HD * HD;      // 128
        float* sMu = sB2 + HD;           // 64
        float* sBe = sMu + 64;           // 64
        float* sBuf = sBe + 64;          // 16 * 364
        const float* W1 = mlpW1 + (size_t)l * NR * HD;
        const float* W2 = mlpW2 + (size_t)l * HD * HD;
        for (int i = tid; i < NR * HD; i += 512) sW1[i] = W1[i];
        for (int i = tid; i < HD * HD; i += 512) sW2[i] = W2[i];
        if (tid < HD) { sB1[tid] = mlpb1[l * HD + tid]; sB2[tid] = mlpb2[l * HD + tid]; }
        if (tid < NR) { sMu[tid] = means[tid]; sBe[tid] = betas[tid]; }
        __syncthreads();
        int warp = tid >> 5, lane = tid & 31;
        float* sEA = sBuf + warp * 364;
        float* sH1 = sEA + 2 * NR;       // stride 132
        int t0 = (blk * 16 + warp) * 2;
        for (int i = lane; i < 2 * NR; i += 32) {
            int e = i / NR, r = i - e * NR;
            float u = UMINF + (float)(t0 + e) * INVTF;
            float d = -logf(u);
            float C = (d < CUTR) ? 0.5f * (cosf(PI_F * d / CUTR) + 1.f) : 0.f;
            float td = u - sMu[r];
            sEA[i] = C * expf(-sBe[r] * td * td);
        }
        __syncwarp();
        float4 acc[2];
        #pragma unroll
        for (int e = 0; e < 2; e++) acc[e] = make_float4(0.f, 0.f, 0.f, 0.f);
        #pragma unroll 2
        for (int r = 0; r < NR; r++) {
            float4 w = *(float4*)&sW1[r * HD + 4 * lane];
            #pragma unroll
            for (int e = 0; e < 2; e++) {
                float a = sEA[e * NR + r];
                acc[e].x = fmaf(a, w.x, acc[e].x);
                acc[e].y = fmaf(a, w.y, acc[e].y);
                acc[e].z = fmaf(a, w.z, acc[e].z);
                acc[e].w = fmaf(a, w.w, acc[e].w);
            }
        }
        float4 b1v = *(float4*)&sB1[4 * lane];
        #pragma unroll
        for (int e = 0; e < 2; e++) {
            int c0 = e * 132 + 4 * lane;
            sH1[c0 + 0] = silu_f(acc[e].x + b1v.x);
            sH1[c0 + 1] = silu_f(acc[e].y + b1v.y);
            sH1[c0 + 2] = silu_f(acc[e].z + b1v.z);
            sH1[c0 + 3] = silu_f(acc[e].w + b1v.w);
            acc[e] = make_float4(0.f, 0.f, 0.f, 0.f);
        }
        __syncwarp();
        #pragma unroll 2
        for (int r = 0; r < HD; r++) {
            float4 w = *(float4*)&sW2[r * HD + 4 * lane];
            #pragma unroll
            for (int e = 0; e < 2; e++) {
                float a = sH1[e * 132 + r];
                acc[e].x = fmaf(a, w.x, acc[e].x);
                acc[e].y = fmaf(a, w.y, acc[e].y);
                acc[e].z = fmaf(a, w.z, acc[e].z);
                acc[e].w = fmaf(a, w.w, acc[e].w);
            }
        }
        float4 b2v = *(float4*)&sB2[4 * lane];
        #pragma unroll
        for (int e = 0; e < 2; e++) {
            int t = t0 + e;
            float u = UMINF + (float)t * INVTF;
            float d = -logf(u);
            float C = (d < CUTR) ? 0.5f * (cosf(PI_F * d / CUTR) + 1.f) : 0.f;
            __half2* p = (__half2*)&g_tblcf_h[((size_t)l * NT + t) * HD + 4 * lane];
            p[0] = __floats2half2_rn((acc[e].x + b2v.x) * C, (acc[e].y + b2v.y) * C);
            p[1] = __floats2half2_rn((acc[e].z + b2v.z) * C, (acc[e].w + b2v.w) * C);
        }
    }
}

// ---------------- scan ----------------
__global__ void scan_kernel() {
    __shared__ int sh[1024];
    int tid = threadIdx.x;
    int base = tid * 10;
    int loc[10];
    int sum = 0;
    #pragma unroll
    for (int k = 0; k < 10; k++) {
        int i = base + k;
        int c = (i < NA) ? g_cnt[i] : 0;
        loc[k] = sum; sum += c;
    }
    sh[tid] = sum;
    __syncthreads();
    for (int off = 1; off < 1024; off <<= 1) {
        int v = 0;
        if (tid >= off) v = sh[tid - off];
        __syncthreads();
        sh[tid] += v;
        __syncthreads();
    }
    int pre = (tid == 0) ? 0 : sh[tid - 1];
    #pragma unroll
    for (int k = 0; k < 10; k++) {
        int i = base + k;
        if (i < NA) { g_off[i] = pre + loc[k]; g_cur[i] = pre + loc[k]; }
    }
    if (tid == 1023) g_off[NA] = sh[1023];
}

// ---------------- CSR fill ----------------
__global__ __launch_bounds__(512)
void geom_fill(const int* __restrict__ ei) {
    int e = blockIdx.x * 512 + threadIdx.x;
    if (e >= NE) return;
    float u = g_tmp[e];
    if (u >= 0.f) {
        int d = ei[NE + e];
        int j = atomicAdd(&g_cur[d], 1);
        g_edge[j] = make_int2(ei[e], __float_as_int(u));
    }
}

// ---------------- scatter (fp16 table + fp16 y) ----------------
__device__ __forceinline__ void edge_acc(int j, int n, int lane, int self_mask,
                                         const __half* __restrict__ TBL,
                                         const __half* __restrict__ Y, float4& acc) {
    int2 ed = __ldg(&g_edge[j]);
    int s = ed.x;
    float u = __int_as_float(ed.y);
    float tf = (u - UMINF) * SCALEF;
    tf = fminf(fmaxf(tf, 0.f), (float)(NT - 1));
    int ti = (int)tf;
    if (ti > NT - 2) ti = NT - 2;
    float fr = tf - (float)ti;
    const uint2* r0 = (const uint2*)TBL + (size_t)ti * (HD / 4) + lane;
    uint2 h0 = __ldg(r0);
    uint2 h1 = __ldg(r0 + HD / 4);
    uint2 hy = __ldg((const uint2*)Y + (size_t)s * (HD / 4) + lane);
    float2 a0 = __half22float2(*(__half2*)&h0.x);
    float2 a1 = __half22float2(*(__half2*)&h0.y);
    float2 b0 = __half22float2(*(__half2*)&h1.x);
    float2 b1 = __half22float2(*(__half2*)&h1.y);
    float2 y0 = __half22float2(*(__half2*)&hy.x);
    float2 y1 = __half22float2(*(__half2*)&hy.y);
    float g = (self_mask && (s == n)) ? 0.f : 1.f;
    float wx = fmaf(fr, b0.x - a0.x, a0.x) * g;
    float wy = fmaf(fr, b0.y - a0.y, a0.y) * g;
    float wz = fmaf(fr, b1.x - a1.x, a1.x) * g;
    float ww = fmaf(fr, b1.y - a1.y, a1.y) * g;
    acc.x = fmaf(y0.x, wx, acc.x);
    acc.y = fmaf(y0.y, wy, acc.y);
    acc.z = fmaf(y1.x, wz, acc.z);
    acc.w = fmaf(y1.y, ww, acc.w);
}

__global__ __launch_bounds__(512)
void scatter_kernel(const __half* __restrict__ TBL, const __half* __restrict__ Y,
                    float* __restrict__ M, int self_mask) {
    int warp = threadIdx.x >> 5, lane = threadIdx.x & 31;
    int n = blockIdx.x * 16 + warp;
    if (n >= NA) return;
    int beg = __ldg(&g_off[n]), end = __ldg(&g_off[n + 1]);
    float4 a0 = make_float4(0.f, 0.f, 0.f, 0.f);
    float4 a1 = make_float4(0.f, 0.f, 0.f, 0.f);
    int j = beg;
    for (; j + 1 < end; j += 2) {
        edge_acc(j, n, lane, self_mask, TBL, Y, a0);
        edge_acc(j + 1, n, lane, self_mask, TBL, Y, a1);
    }
    if (j < end) edge_acc(j, n, lane, self_mask, TBL, Y, a0);
    a0.x += a1.x; a0.y += a1.y; a0.z += a1.z; a0.w += a1.w;
    *(float4*)(M + (size_t)n * HD + 4 * lane) = a0;
}

// ---------- comb_mm: x = [x,msg]@Wc+bc ; y0 = x@W1 (fp16 out) ----------
__global__ __launch_bounds__(224, 1)
void comb_mm(const float* __restrict__ Wc, const float* __restrict__ bc,
             const float* __restrict__ W1) {
    extern __shared__ float sh[];
    float* sWc = sh;                     // 32768 floats
    float* sW1 = sh + 256 * HD;          // 16384 floats
    __half* sTh = (__half*)(sh + 256 * HD + HD * HD);  // 7*1280 halves
    int tid = threadIdx.x;
    for (int i = tid; i < 256 * HD; i += 224) sWc[i] = Wc[i];
    for (int i = tid; i < HD * HD; i += 224) sW1[i] = W1[i];
    __syncthreads();
    int warp = tid >> 5, lane = tid & 31;
    __half* sX = sTh + warp * 1280;
    float4 bcf = __ldg((const float4*)bc + lane);
    ull bca = pack2(bcf.x, bcf.y), bcb = pack2(bcf.z, bcf.w);
    for (int pass = 0; pass < 2; pass++) {
        int gw = blockIdx.x * F3W + warp + pass * (NBLK * F3W);
        int n0 = gw * CMN;
        __syncwarp();
        // stage in [x|msg] rows as fp16
        for (int i = lane; i < CMN * 64; i += 32) {
            int nn = i >> 6, c = i & 63;
            int node = min(n0 + nn, NA - 1);
            float4 v = (c < 32)
                ? __ldg((const float4*)(g_x + (size_t)node * HD) + c)
                : __ldg((const float4*)(g_msg + (size_t)node * HD) + (c - 32));
            __half2 h0 = __floats2half2_rn(v.x, v.y);
            __half2 h1 = __floats2half2_rn(v.z, v.w);
            uint2 st; st.x = *(unsigned*)&h0; st.y = *(unsigned*)&h1;
            ((uint2*)sX)[i] = st;
        }
        __syncwarp();
        ull acc[CMN][2];
        #pragma unroll
        for (int nn = 0; nn < CMN; nn++) { acc[nn][0] = bca; acc[nn][1] = bcb; }
        for (int r2 = 0; r2 < 128; r2++) {
            ulonglong2 w0 = *(ulonglong2*)&sWc[(2 * r2) * HD + 4 * lane];
            ulonglong2 w1 = *(ulonglong2*)&sWc[(2 * r2 + 1) * HD + 4 * lane];
            #pragma unroll
            for (int nn = 0; nn < CMN; nn++) {
                float2 af = __half22float2(((__half2*)sX)[nn * 128 + r2]);
                ull aa = dup2(af.x), ab = dup2(af.y);
                acc[nn][0] = ffma2(aa, w0.x, acc[nn][0]);
                acc[nn][1] = ffma2(aa, w0.y, acc[nn][1]);
                acc[nn][0] = ffma2(ab, w1.x, acc[nn][0]);
                acc[nn][1] = ffma2(ab, w1.y, acc[nn][1]);
            }
        }
        __syncwarp();
        #pragma unroll
        for (int nn = 0; nn < CMN; nn++) {
            int node = n0 + nn;
            float4 v = make_float4(lo32(acc[nn][0]), hi32(acc[nn][0]),
                                   lo32(acc[nn][1]), hi32(acc[nn][1]));
            if (node < NA) *(float4*)&g_x[(size_t)node * HD + 4 * lane] = v;
            ((__half2*)sX)[nn * 64 + 2 * lane] = __floats2half2_rn(v.x, v.y);
            ((__half2*)sX)[nn * 64 + 2 * lane + 1] = __floats2half2_rn(v.z, v.w);
            acc[nn][0] = 0ull; acc[nn][1] = 0ull;
        }
        __syncwarp();
        for (int r2 = 0; r2 < 64; r2++) {
            ulonglong2 w0 = *(ulonglong2*)&sW1[(2 * r2) * HD + 4 * lane];
            ulonglong2 w1 = *(ulonglong2*)&sW1[(2 * r2 + 1) * HD + 4 * lane];
            #pragma unroll
            for (int nn = 0; nn < CMN; nn++) {
                float2 af = __half22float2(((__half2*)sX)[nn * 64 + r2]);
                ull aa = dup2(af.x), ab = dup2(af.y);
                acc[nn][0] = ffma2(aa, w0.x, acc[nn][0]);
                acc[nn][1] = ffma2(aa, w0.y, acc[nn][1]);
                acc[nn][0] = ffma2(ab, w1.x, acc[nn][0]);
                acc[nn][1] = ffma2(ab, w1.y, acc[nn][1]);
            }
        }
        #pragma unroll
        for (int nn = 0; nn < CMN; nn++) {
            int node = n0 + nn;
            if (node >= NA) continue;
            ((__half2*)g_yh)[(size_t)node * 64 + 2 * lane] =
                __floats2half2_rn(lo32(acc[nn][0]), hi32(acc[nn][0]));
            ((__half2*)g_yh)[(size_t)node * 64 + 2 * lane + 1] =
                __floats2half2_rn(lo32(acc[nn][1]), hi32(acc[nn][1]));
        }
    }
}

// ------- fused3: t=silu(M@W2+b2); xn=X+t@WL+bL -> xout; y=xn@W1n -> yout (fp16) -------
__global__ __launch_bounds__(224, 1)
void fused3(const float* __restrict__ M,
            const float* __restrict__ W2, const float* __restrict__ b2,
            const float* __restrict__ WL, const float* __restrict__ bL,
            const float* __restrict__ W1n,
            const float* __restrict__ X,
            float* __restrict__ xout, __half* __restrict__ yout) {
    extern __shared__ float sh[];
    float* sW2 = sh;
    float* sWL = sh + HD * HD;
    float* sW1 = sh + 2 * HD * HD;
    __half* sTh = (__half*)(sh + 3 * HD * HD);   // 7*1280 halves
    int tid = threadIdx.x;
    for (int i = tid; i < HD * HD; i += 224) {
        sW2[i] = W2[i];
        sWL[i] = WL[i];
        if (W1n) sW1[i] = W1n[i];
    }
    __syncthreads();
    int warp = tid >> 5, lane = tid & 31;
    __half* sX = sTh + warp * 1280;
    int gw = blockIdx.x * F3W + warp;
    int n0 = gw * F3N;
    float4 b2f = __ldg((const float4*)b2 + lane);
    float4 bLf = __ldg((const float4*)bL + lane);
    ull b2a = pack2(b2f.x, b2f.y), b2b = pack2(b2f.z, b2f.w);
    ull bLa = pack2(bLf.x, bLf.y), bLb = pack2(bLf.z, bLf.w);
    // stage in M rows as fp16
    for (int i = lane; i < F3N * 32; i += 32) {
        int nn = i >> 5, c = i & 31;
        int node = min(n0 + nn, NA - 1);
        float4 v = __ldg((const float4*)(M + (size_t)node * HD) + c);
        __half2 h0 = __floats2half2_rn(v.x, v.y);
        __half2 h1 = __floats2half2_rn(v.z, v.w);
        uint2 st; st.x = *(unsigned*)&h0; st.y = *(unsigned*)&h1;
        ((uint2*)sX)[i] = st;
    }
    __syncwarp();
    ull acc[F3N][2];
    #pragma unroll
    for (int nn = 0; nn < F3N; nn++) { acc[nn][0] = b2a; acc[nn][1] = b2b; }
    // stage 1: M @ W2 + b2
    for (int r2 = 0; r2 < 64; r2++) {
        ulonglong2 w0 = *(ulonglong2*)&sW2[(2 * r2) * HD + 4 * lane];
        ulonglong2 w1 = *(ulonglong2*)&sW2[(2 * r2 + 1) * HD + 4 * lane];
        #pragma unroll
        for (int nn = 0; nn < F3N; nn++) {
            float2 af = __half22float2(((__half2*)sX)[nn * 64 + r2]);
            ull aa = dup2(af.x), ab = dup2(af.y);
            acc[nn][0] = ffma2(aa, w0.x, acc[nn][0]);
            acc[nn][1] = ffma2(aa, w0.y, acc[nn][1]);
            acc[nn][0] = ffma2(ab, w1.x, acc[nn][0]);
            acc[nn][1] = ffma2(ab, w1.y, acc[nn][1]);
        }
    }
    __syncwarp();
    #pragma unroll
    for (int nn = 0; nn < F3N; nn++) {
        float t0 = silu_f(lo32(acc[nn][0])), t1 = silu_f(hi32(acc[nn][0]));
        float t2 = silu_f(lo32(acc[nn][1])), t3 = silu_f(hi32(acc[nn][1]));
        ((__half2*)sX)[nn * 64 + 2 * lane] = __floats2half2_rn(t0, t1);
        ((__half2*)sX)[nn * 64 + 2 * lane + 1] = __floats2half2_rn(t2, t3);
        acc[nn][0] = bLa; acc[nn][1] = bLb;
    }
    __syncwarp();
    // stage 2: t @ WL + bL
    for (int r2 = 0; r2 < 64; r2++) {
        ulonglong2 w0 = *(ulonglong2*)&sWL[(2 * r2) * HD + 4 * lane];
        ulonglong2 w1 = *(ulonglong2*)&sWL[(2 * r2 + 1) * HD + 4 * lane];
        #pragma unroll
        for (int nn = 0; nn < F3N; nn++) {
            float2 af = __half22float2(((__half2*)sX)[nn * 64 + r2]);
            ull aa = dup2(af.x), ab = dup2(af.y);
            acc[nn][0] = ffma2(aa, w0.x, acc[nn][0]);
            acc[nn][1] = ffma2(aa, w0.y, acc[nn][1]);
            acc[nn][0] = ffma2(ab, w1.x, acc[nn][0]);
            acc[nn][1] = ffma2(ab, w1.y, acc[nn][1]);
        }
    }
    __syncwarp();
    // residual + store x_new
    #pragma unroll
    for (int nn = 0; nn < F3N; nn++) {
        int node = n0 + nn;
        float4 xv = make_float4(0.f, 0.f, 0.f, 0.f);
        if (node < NA) xv = __ldg((const float4*)(X + (size_t)node * HD) + lane);
        float4 v;
        v.x = xv.x + lo32(acc[nn][0]);
        v.y = xv.y + hi32(acc[nn][0]);
        v.z = xv.z + lo32(acc[nn][1]);
        v.w = xv.w + hi32(acc[nn][1]);
        if (node < NA) *(float4*)&xout[(size_t)node * HD + 4 * lane] = v;
        ((__half2*)sX)[nn * 64 + 2 * lane] = __floats2half2_rn(v.x, v.y);
        ((__half2*)sX)[nn * 64 + 2 * lane + 1] = __floats2half2_rn(v.z, v.w);
        acc[nn][0] = 0ull; acc[nn][1] = 0ull;
    }
    if (W1n) {
        __syncwarp();
        // stage 3: y_next = x_new @ W1n
        for (int r2 = 0; r2 < 64; r2++) {
            ulonglong2 w0 = *(ulonglong2*)&sW1[(2 * r2) * HD + 4 * lane];
            ulonglong2 w1 = *(ulonglong2*)&sW1[(2 * r2 + 1) * HD + 4 * lane];
            #pragma unroll
            for (int nn = 0; nn < F3N; nn++) {
                float2 af = __half22float2(((__half2*)sX)[nn * 64 + r2]);
                ull aa = dup2(af.x), ab = dup2(af.y);
                acc[nn][0] = ffma2(aa, w0.x, acc[nn][0]);
                acc[nn][1] = ffma2(aa, w0.y, acc[nn][1]);
                acc[nn][0] = ffma2(ab, w1.x, acc[nn][0]);
                acc[nn][1] = ffma2(ab, w1.y, acc[nn][1]);
            }
        }
        #pragma unroll
        for (int nn = 0; nn < F3N; nn++) {
            int node = n0 + nn;
            if (node >= NA) continue;
            ((__half2*)yout)[(size_t)node * 64 + 2 * lane] =
                __floats2half2_rn(lo32(acc[nn][0]), hi32(acc[nn][0]));
            ((__half2*)yout)[(size_t)node * 64 + 2 * lane + 1] =
                __floats2half2_rn(lo32(acc[nn][1]), hi32(acc[nn][1]));
        }
    }
}

// ---------------- launcher ----------------
extern "C" void kernel_launch(void* const* d_in, const int* in_sizes, int n_in,
                              void* d_out, int out_size) {
    const int*   z      = (const int*)d_in[0];
    const float* pos    = (const float*)d_in[1];
    const int*   ei     = (const int*)d_in[3];
    const float* emb    = (const float*)d_in[4];
    const float* nemb   = (const float*)d_in[5];
    const float* nprojW = (const float*)d_in[6];
    const float* nprojB = (const float*)d_in[7];
    const float* ncombW = (const float*)d_in[8];
    const float* ncombB = (const float*)d_in[9];
    const float* means  = (const float*)d_in[10];
    const float* betas  = (const float*)d_in[11];
    const float* mlpW1  = (const float*)d_in[12];
    const float* mlpb1  = (const float*)d_in[13];
    const float* mlpW2  = (const float*)d_in[14];
    const float* mlpb2  = (const float*)d_in[15];
    const float* convW1 = (const float*)d_in[16];
    const float* convW2 = (const float*)d_in[17];
    const float* convb2 = (const float*)d_in[18];
    const float* linW   = (const float*)d_in[19];
    const float* linb   = (const float*)d_in[20];
    float* out = (float*)d_out;

    void *p_cnt, *p_x, *p_yh, *p_m, *p_msg, *p_tc, *p_tn;
    cudaGetSymbolAddress(&p_cnt, g_cnt);
    cudaGetSymbolAddress(&p_x, g_x);
    cudaGetSymbolAddress(&p_yh, g_yh);
    cudaGetSymbolAddress(&p_m, g_m);
    cudaGetSymbolAddress(&p_msg, g_msg);
    cudaGetSymbolAddress(&p_tc, g_tblcf_h);
    cudaGetSymbolAddress(&p_tn, g_tbln_h);
    float* px = (float*)p_x;
    __half* pyh = (__half*)p_yh;
    float* pm = (float*)p_m;
    float* pmsg = (float*)p_msg;
    __half* ptc = (__half*)p_tc;
    __half* ptn = (__half*)p_tn;

    size_t sh_mega = (size_t)28992 * sizeof(float);                        // 115968
    size_t sh_cm   = (size_t)(256 * HD + HD * HD) * sizeof(float) + 17920; // 214528
    size_t sh_f3   = (size_t)(3 * HD * HD) * sizeof(float) + 17920;        // 214528
    cudaFuncSetAttribute(mega_setup, cudaFuncAttributeMaxDynamicSharedMemorySize, (int)sh_mega);
    cudaFuncSetAttribute(comb_mm,    cudaFuncAttributeMaxDynamicSharedMemorySize, (int)sh_cm);
    cudaFuncSetAttribute(fused3,     cudaFuncAttributeMaxDynamicSharedMemorySize, (int)sh_f3);

    cudaMemsetAsync(p_cnt, 0, NA * sizeof(int));
    mega_setup<<<1081, 512, sh_mega>>>(ei, pos, z, emb, nemb, means, betas,
                                       nprojW, nprojB, mlpW1, mlpb1, mlpW2, mlpb2);
    scan_kernel<<<1, 1024>>>();
    geom_fill<<<625, 512>>>(ei);
    scatter_kernel<<<625, 512>>>(ptn, pyh, pmsg, 1);
    comb_mm<<<NBLK, 224, sh_cm>>>(ncombW, ncombB, convW1);

    for (int l = 0; l < NL; l++) {
        scatter_kernel<<<625, 512>>>(ptc + (size_t)l * NT * HD, pyh, pm, 0);
        float* dest = (l == NL - 1) ? out : px;
        const float* W1n = (l == NL - 1) ? nullptr : (convW1 + (size_t)(l + 1) * HD * HD);
        fused3<<<NBLK, 224, sh_f3>>>(pm, convW2 + (size_t)l * HD * HD,
                                     convb2 + (size_t)l * HD,
                                     linW + (size_t)l * HD * HD,
                                     linb + (size_t)l * HD,
                                     W1n, px, dest, pyh);
    }
}